// round 8
// baseline (speedup 1.0000x reference)
#include <cuda_runtime.h>
#include <cuda_fp16.h>
#include <cstdint>

#define GG 512            // B*T graphs
#define NN 500            // nodes
#define FIN 96
#define HID 64
#define OUTF 96
#define ROWS (GG*NN)      // 256000
#define BN_EPS 1e-5f
#define NNZ_MAX (NN*NN)
#define SLICE 63          // rows per spmm block
#define ECAP 3072         // staged ecsr entries per block (24KB)

// ---------------- scratch (device globals; no allocation allowed) ----------------
__device__ __half2 g_t16[(long)ROWS*HID/2]; // GEMM output / SpMM input (fp16)
__device__ float g_s[(long)ROWS*HID];    // SpMM output
__device__ float g_h[(long)ROWS*HID];    // layer activations (residual chain)
__device__ float g_r[(long)ROWS*HID];    // layer-0 residual (x @ w_r0 + b_r0)
__device__ float g_dinv[NN];
__device__ int   g_cnt[NN];
__device__ int   g_rowptr[NN+1];
__device__ float2 g_ecsr[NNZ_MAX];       // packed (col-as-int-bits, val)
__device__ float g_sum[HID];
__device__ float g_sumsq[HID];
__device__ float g_scale[HID];
__device__ float g_shift[HID];

// ---------------- prep 1: degrees / dinv + per-row nnz counts ----------------
__global__ void prep_deg(const float* __restrict__ adj) {
    int m = blockIdx.x;
    int tid = threadIdx.x;
    float sum = 0.f; int cnt = 0;
    for (int n = tid; n < NN; n += blockDim.x) {
        float a = adj[m*NN + n];
        sum += a;
        cnt += (a != 0.f) ? 1 : 0;
    }
    __shared__ float ssum[4]; __shared__ int scnt[4];
    #pragma unroll
    for (int o = 16; o; o >>= 1) {
        sum += __shfl_down_sync(0xFFFFFFFFu, sum, o);
        cnt += __shfl_down_sync(0xFFFFFFFFu, cnt, o);
    }
    int w = tid >> 5;
    if ((tid & 31) == 0) { ssum[w] = sum; scnt[w] = cnt; }
    __syncthreads();
    if (tid == 0) {
        float s = ssum[0] + ssum[1] + ssum[2] + ssum[3];
        int c = scnt[0] + scnt[1] + scnt[2] + scnt[3];
        g_dinv[m] = rsqrtf(1.f + s);
        g_cnt[m] = c + 1;   // + diagonal
    }
    if (blockIdx.x == 0 && tid < HID) { g_sum[tid] = 0.f; g_sumsq[tid] = 0.f; }
}

// ---------------- prep 2: scan rowptr + fill CSR (single block, deterministic) ----
// fill reads adj[n][m] (== adj[m][n] by symmetry) so loads stay coalesced across m.
__global__ void prep_scanfill(const float* __restrict__ adj) {
    __shared__ int sc[512];
    int tid = threadIdx.x;
    sc[tid] = (tid < NN) ? g_cnt[tid] : 0;
    __syncthreads();
    for (int off = 1; off < 512; off <<= 1) {
        int v = (tid >= off) ? sc[tid - off] : 0;
        __syncthreads();
        sc[tid] += v;
        __syncthreads();
    }
    if (tid < NN) g_rowptr[tid + 1] = sc[tid];
    if (tid == 0) g_rowptr[0] = 0;
    __syncthreads();
    if (tid < NN) {
        int m = tid;
        float dm = g_dinv[m];
        int p = g_rowptr[m];
        for (int n = 0; n < NN; n++) {
            if (n == m) {
                g_ecsr[p] = make_float2(__int_as_float(m), dm * dm);
                p++;
            } else {
                float a = adj[n*NN + m];   // symmetric read, coalesced across tid
                if (a != 0.f) {
                    g_ecsr[p] = make_float2(__int_as_float(n), dm * a * g_dinv[n]);
                    p++;
                }
            }
        }
    }
}

// ---------------- tensor-core GEMM (3xTF32 split, fp32-equivalent accuracy) -------
__device__ __forceinline__ void tf32_split(float x, uint32_t& hi, uint32_t& lo) {
    asm("cvt.rna.tf32.f32 %0, %1;" : "=r"(hi) : "f"(x));
    float r = x - __uint_as_float(hi);
    asm("cvt.rna.tf32.f32 %0, %1;" : "=r"(lo) : "f"(r));
}

__device__ __forceinline__ void mma_tf32(float* c, const uint32_t* a, const uint32_t* b) {
    asm volatile(
        "mma.sync.aligned.m16n8k8.row.col.f32.tf32.tf32.f32 "
        "{%0,%1,%2,%3}, {%4,%5,%6,%7}, {%8,%9}, {%0,%1,%2,%3};\n"
        : "+f"(c[0]), "+f"(c[1]), "+f"(c[2]), "+f"(c[3])
        : "r"(a[0]), "r"(a[1]), "r"(a[2]), "r"(a[3]), "r"(b[0]), "r"(b[1]));
}

#define GEMM_SMEM_WORDS (4608*2 + 2304*2)
#define GEMM_SMEM_BYTES (GEMM_SMEM_WORDS * 4)

template<int K, int C, bool ACCUM, bool FUSE, bool WRITE_H, bool OUT_HALF>
__global__ __launch_bounds__(256) void gemm_tc(
    const float* __restrict__ A, const float* __restrict__ R, float* __restrict__ Hout,
    const float* __restrict__ Bw, const float* __restrict__ bias, void* __restrict__ Cout)
{
    extern __shared__ uint32_t dsm[];
    uint32_t (*AsH)[36] = (uint32_t(*)[36])(dsm);
    uint32_t (*AsL)[36] = (uint32_t(*)[36])(dsm + 4608);
    uint32_t (*BsH)[72] = (uint32_t(*)[72])(dsm + 9216);
    uint32_t (*BsL)[72] = (uint32_t(*)[72])(dsm + 11520);
    __shared__ float s_scale[HID], s_shift[HID];

    const int tid = threadIdx.x;
    const int wid = tid >> 5;
    const int lane = tid & 31;
    const int g  = lane >> 2;
    const int t4 = lane & 3;
    const int warp_m = wid >> 1;
    const int warp_n = wid & 1;

    const long row0 = (long)blockIdx.x * 128;
    const int col0 = blockIdx.y * 64;

    if (FUSE) {
        if (tid < HID) s_scale[tid] = g_scale[tid];
        else if (tid < 2*HID) s_shift[tid - HID] = g_shift[tid - HID];
        __syncthreads();
    }

    float acc[2][4][4];
    #pragma unroll
    for (int mt = 0; mt < 2; mt++)
        #pragma unroll
        for (int nt = 0; nt < 4; nt++)
            #pragma unroll
            for (int q = 0; q < 4; q++) acc[mt][nt][q] = 0.f;

    for (int k0 = 0; k0 < K; k0 += 32) {
        #pragma unroll
        for (int i = 0; i < 4; i++) {
            int idx = tid + i * 256;
            int r = idx >> 3;
            int q = idx & 7;
            long off = (row0 + r) * K + (k0 + q * 4);
            float4 v = *(const float4*)(A + off);
            if (FUSE) {
                int kc = k0 + q * 4;
                float4 rv = *(const float4*)(R + off);
                v.x = fmaxf(v.x * s_scale[kc+0] + s_shift[kc+0], 0.f) + rv.x;
                v.y = fmaxf(v.y * s_scale[kc+1] + s_shift[kc+1], 0.f) + rv.y;
                v.z = fmaxf(v.z * s_scale[kc+2] + s_shift[kc+2], 0.f) + rv.z;
                v.w = fmaxf(v.w * s_scale[kc+3] + s_shift[kc+3], 0.f) + rv.w;
                if (WRITE_H) *(float4*)(Hout + off) = v;
            }
            uint4 hi, lo;
            tf32_split(v.x, hi.x, lo.x);
            tf32_split(v.y, hi.y, lo.y);
            tf32_split(v.z, hi.z, lo.z);
            tf32_split(v.w, hi.w, lo.w);
            *(uint4*)&AsH[r][q*4] = hi;
            *(uint4*)&AsL[r][q*4] = lo;
        }
        #pragma unroll
        for (int i = 0; i < 2; i++) {
            int idx = tid + i * 256;
            int kk = idx >> 4;
            int q = idx & 15;
            int c = col0 + q * 4;
            float4 v = make_float4(0.f, 0.f, 0.f, 0.f);
            if ((C & 63) == 0 || c < C)
                v = *(const float4*)(Bw + (k0 + kk) * C + c);
            uint4 hi, lo;
            tf32_split(v.x, hi.x, lo.x);
            tf32_split(v.y, hi.y, lo.y);
            tf32_split(v.z, hi.z, lo.z);
            tf32_split(v.w, hi.w, lo.w);
            *(uint4*)&BsH[kk][q*4] = hi;
            *(uint4*)&BsL[kk][q*4] = lo;
        }
        __syncthreads();

        #pragma unroll
        for (int kk = 0; kk < 4; kk++) {
            uint32_t ahi[2][4], alo[2][4];
            #pragma unroll
            for (int mt = 0; mt < 2; mt++) {
                int r = warp_m * 32 + mt * 16 + g;
                int kc = kk * 8 + t4;
                ahi[mt][0] = AsH[r][kc];     alo[mt][0] = AsL[r][kc];
                ahi[mt][1] = AsH[r+8][kc];   alo[mt][1] = AsL[r+8][kc];
                ahi[mt][2] = AsH[r][kc+4];   alo[mt][2] = AsL[r][kc+4];
                ahi[mt][3] = AsH[r+8][kc+4]; alo[mt][3] = AsL[r+8][kc+4];
            }
            uint32_t bhi[4][2], blo[4][2];
            #pragma unroll
            for (int nt = 0; nt < 4; nt++) {
                int nb = warp_n * 32 + nt * 8 + g;
                int kr = kk * 8 + t4;
                bhi[nt][0] = BsH[kr][nb];    blo[nt][0] = BsL[kr][nb];
                bhi[nt][1] = BsH[kr+4][nb];  blo[nt][1] = BsL[kr+4][nb];
            }
            #pragma unroll
            for (int mt = 0; mt < 2; mt++)
                #pragma unroll
                for (int nt = 0; nt < 4; nt++) {
                    mma_tf32(acc[mt][nt], ahi[mt], bhi[nt]);
                    mma_tf32(acc[mt][nt], ahi[mt], blo[nt]);
                    mma_tf32(acc[mt][nt], alo[mt], bhi[nt]);
                }
        }
        __syncthreads();
    }

    #pragma unroll
    for (int mt = 0; mt < 2; mt++) {
        long rowa = row0 + warp_m * 32 + mt * 16 + g;
        long rowb = rowa + 8;
        #pragma unroll
        for (int nt = 0; nt < 4; nt++) {
            int col = col0 + warp_n * 32 + nt * 8 + 2 * t4;
            if ((C & 63) == 0 || col < C) {
                float bx = bias[col];
                float by = bias[col + 1];
                float2 v0 = make_float2(acc[mt][nt][0] + bx, acc[mt][nt][1] + by);
                float2 v1 = make_float2(acc[mt][nt][2] + bx, acc[mt][nt][3] + by);
                if (OUT_HALF) {
                    __half2* o = (__half2*)Cout;
                    o[(rowa * C + col) >> 1] = __floats2half2_rn(v0.x, v0.y);
                    o[(rowb * C + col) >> 1] = __floats2half2_rn(v1.x, v1.y);
                } else {
                    float* d0 = (float*)Cout + rowa * C + col;
                    float* d1 = (float*)Cout + rowb * C + col;
                    if (ACCUM) {
                        float2 o0 = *(const float2*)d0;
                        float2 o1 = *(const float2*)d1;
                        v0.x += o0.x; v0.y += o0.y;
                        v1.x += o1.x; v1.y += o1.y;
                    }
                    *(float2*)d0 = v0;
                    *(float2*)d1 = v1;
                }
            }
        }
    }
}

// ---------------- SpMM (s = a_hat @ t per graph) + BN stats partials ----------------
// grid (8, GG), blockDim (16,16): 63-row slices. The block's ecsr slice is staged
// into smem (coalesced), so the inner loop's (col,val) read is a 29-cyc LDS
// broadcast instead of a dependent 234-cyc LDG before every gather.
__global__ __launch_bounds__(256) void spmm_stats(
    const __half2* __restrict__ T2, float* __restrict__ S)
{
    __shared__ float2 se[ECAP];
    __shared__ float red[16][64];

    int g = blockIdx.y;
    int m0 = blockIdx.x * SLICE;
    int mend = min(m0 + SLICE, NN);
    int cx = threadIdx.x;
    int c4 = cx * 4;
    int yr = threadIdx.y;
    int tid = yr * 16 + cx;
    const __half2* tg = T2 + (long)g * NN * (HID/2);
    float* sg = S + (long)g * NN * HID;

    int base = g_rowptr[m0];
    int cnt = g_rowptr[mend] - base;
    int scount = min(cnt, ECAP);
    for (int i = tid; i < scount; i += 256) se[i] = g_ecsr[base + i];
    __syncthreads();

    float lsum[4] = {0,0,0,0}, lsq[4] = {0,0,0,0};

    for (int m = m0 + yr; m < mend; m += 16) {
        int jb = g_rowptr[m] - base, je = g_rowptr[m + 1] - base;
        float4 a0 = make_float4(0.f, 0.f, 0.f, 0.f);
        float4 a1 = make_float4(0.f, 0.f, 0.f, 0.f);
        if (je <= ECAP) {
            int j = jb;
            for (; j + 3 < je; j += 4) {
                float2 cv0 = se[j],     cv1 = se[j + 1];
                float2 cv2 = se[j + 2], cv3 = se[j + 3];
                int   c0 = __float_as_int(cv0.x), c1 = __float_as_int(cv1.x);
                int   c2 = __float_as_int(cv2.x), c3 = __float_as_int(cv3.x);
                float w0 = cv0.y, w1 = cv1.y, w2 = cv2.y, w3 = cv3.y;
                uint2 r0 = *(const uint2*)(tg + c0 * (HID/2) + cx * 2);
                uint2 r1 = *(const uint2*)(tg + c1 * (HID/2) + cx * 2);
                uint2 r2 = *(const uint2*)(tg + c2 * (HID/2) + cx * 2);
                uint2 r3 = *(const uint2*)(tg + c3 * (HID/2) + cx * 2);
                float2 t0a = __half22float2(*(__half2*)&r0.x), t0b = __half22float2(*(__half2*)&r0.y);
                float2 t1a = __half22float2(*(__half2*)&r1.x), t1b = __half22float2(*(__half2*)&r1.y);
                float2 t2a = __half22float2(*(__half2*)&r2.x), t2b = __half22float2(*(__half2*)&r2.y);
                float2 t3a = __half22float2(*(__half2*)&r3.x), t3b = __half22float2(*(__half2*)&r3.y);
                a0.x += w0 * t0a.x + w1 * t1a.x;  a1.x += w2 * t2a.x + w3 * t3a.x;
                a0.y += w0 * t0a.y + w1 * t1a.y;  a1.y += w2 * t2a.y + w3 * t3a.y;
                a0.z += w0 * t0b.x + w1 * t1b.x;  a1.z += w2 * t2b.x + w3 * t3b.x;
                a0.w += w0 * t0b.y + w1 * t1b.y;  a1.w += w2 * t2b.y + w3 * t3b.y;
            }
            for (; j < je; j++) {
                float2 cv = se[j];
                int col = __float_as_int(cv.x);
                float w = cv.y;
                uint2 r = *(const uint2*)(tg + col * (HID/2) + cx * 2);
                float2 ta = __half22float2(*(__half2*)&r.x), tb = __half22float2(*(__half2*)&r.y);
                a0.x += w * ta.x; a0.y += w * ta.y;
                a0.z += w * tb.x; a0.w += w * tb.y;
            }
        } else {
            // statistically-never fallback (slice overflowed smem cap)
            for (int j = jb; j < je; j++) {
                float2 cv = g_ecsr[base + j];
                int col = __float_as_int(cv.x);
                float w = cv.y;
                uint2 r = *(const uint2*)(tg + col * (HID/2) + cx * 2);
                float2 ta = __half22float2(*(__half2*)&r.x), tb = __half22float2(*(__half2*)&r.y);
                a0.x += w * ta.x; a0.y += w * ta.y;
                a0.z += w * tb.x; a0.w += w * tb.y;
            }
        }
        float4 acc = make_float4(a0.x + a1.x, a0.y + a1.y, a0.z + a1.z, a0.w + a1.w);
        *(float4*)(sg + m * HID + c4) = acc;
        lsum[0] += acc.x; lsum[1] += acc.y; lsum[2] += acc.z; lsum[3] += acc.w;
        lsq[0] += acc.x * acc.x; lsq[1] += acc.y * acc.y;
        lsq[2] += acc.z * acc.z; lsq[3] += acc.w * acc.w;
    }

    #pragma unroll
    for (int k = 0; k < 4; k++) red[yr][c4 + k] = lsum[k];
    __syncthreads();
    for (int off = 8; off >= 1; off >>= 1) {
        if (yr < off)
            #pragma unroll
            for (int k = 0; k < 4; k++) red[yr][c4 + k] += red[yr + off][c4 + k];
        __syncthreads();
    }
    if (yr == 0)
        #pragma unroll
        for (int k = 0; k < 4; k++) atomicAdd(&g_sum[c4 + k], red[0][c4 + k]);
    __syncthreads();
    #pragma unroll
    for (int k = 0; k < 4; k++) red[yr][c4 + k] = lsq[k];
    __syncthreads();
    for (int off = 8; off >= 1; off >>= 1) {
        if (yr < off)
            #pragma unroll
            for (int k = 0; k < 4; k++) red[yr][c4 + k] += red[yr + off][c4 + k];
        __syncthreads();
    }
    if (yr == 0)
        #pragma unroll
        for (int k = 0; k < 4; k++) atomicAdd(&g_sumsq[c4 + k], red[0][c4 + k]);
}

// ---------------- BN finalize ----------------
__global__ void bn_finalize(const float* __restrict__ gamma, const float* __restrict__ beta) {
    int c = threadIdx.x;
    float s = g_sum[c], q = g_sumsq[c];
    const float inv = 1.f / (float)ROWS;
    float mean = s * inv;
    float var = q * inv - mean * mean;
    float rstd = rsqrtf(var + BN_EPS);
    float a = rstd * gamma[c];
    g_scale[c] = a;
    g_shift[c] = beta[c] - mean * a;
    g_sum[c] = 0.f; g_sumsq[c] = 0.f;
}

// ---------------- launch ----------------
extern "C" void kernel_launch(void* const* d_in, const int* in_sizes, int n_in,
                              void* d_out, int out_size)
{
    const float* x     = (const float*)d_in[0];
    const float* adj   = (const float*)d_in[1];
    const float* w_g0  = (const float*)d_in[2];
    const float* b_g0  = (const float*)d_in[3];
    const float* w_g1  = (const float*)d_in[4];
    const float* b_g1  = (const float*)d_in[5];
    const float* w_g2  = (const float*)d_in[6];
    const float* b_g2  = (const float*)d_in[7];
    const float* gamma = (const float*)d_in[8];
    const float* beta  = (const float*)d_in[9];
    const float* w_r0  = (const float*)d_in[10];
    const float* b_r0  = (const float*)d_in[11];
    const float* w_fc  = (const float*)d_in[12];
    const float* b_fc  = (const float*)d_in[13];
    const float* w_fr  = (const float*)d_in[14];
    const float* b_fr  = (const float*)d_in[15];
    float* out = (float*)d_out;

    __half2 *pt16;
    float *ps, *ph, *pr;
    cudaGetSymbolAddress((void**)&pt16, g_t16);
    cudaGetSymbolAddress((void**)&ps, g_s);
    cudaGetSymbolAddress((void**)&ph, g_h);
    cudaGetSymbolAddress((void**)&pr, g_r);

    const int ROWB = ROWS / 128;               // 2000

    cudaFuncSetAttribute(gemm_tc<FIN, HID, false, false, false, true>,
                         cudaFuncAttributeMaxDynamicSharedMemorySize, GEMM_SMEM_BYTES);
    cudaFuncSetAttribute(gemm_tc<FIN, HID, false, false, false, false>,
                         cudaFuncAttributeMaxDynamicSharedMemorySize, GEMM_SMEM_BYTES);
    cudaFuncSetAttribute(gemm_tc<FIN, OUTF, false, false, false, false>,
                         cudaFuncAttributeMaxDynamicSharedMemorySize, GEMM_SMEM_BYTES);
    cudaFuncSetAttribute(gemm_tc<HID, HID, false, true, true, true>,
                         cudaFuncAttributeMaxDynamicSharedMemorySize, GEMM_SMEM_BYTES);
    cudaFuncSetAttribute(gemm_tc<HID, OUTF, true, true, false, false>,
                         cudaFuncAttributeMaxDynamicSharedMemorySize, GEMM_SMEM_BYTES);

    // #0: t0 = fp16(x@w_g0+b)  (no prep deps; placed first so spmm0 lands in
    //     the ncu capture slot at our launch index 3)
    gemm_tc<FIN, HID, false, false, false, true><<<dim3(ROWB, 1), 256, GEMM_SMEM_BYTES>>>(x, nullptr, nullptr, w_g0, b_g0, pt16);

    // #1,#2: CSR of a_hat (deterministic)
    prep_deg<<<NN, 128>>>(adj);
    prep_scanfill<<<1, 512>>>(adj);

    // #3: layer-0 SpMM  ← ncu capture target
    spmm_stats<<<dim3(8, GG), dim3(16, 16)>>>(pt16, ps);
    bn_finalize<<<1, HID>>>(gamma + 0 * HID, beta + 0 * HID);

    // remaining input GEMMs
    gemm_tc<FIN, HID, false, false, false, false><<<dim3(ROWB, 1), 256, GEMM_SMEM_BYTES>>>(x, nullptr, nullptr, w_r0, b_r0, pr);
    gemm_tc<FIN, OUTF, false, false, false, false><<<dim3(ROWB, 2), 256, GEMM_SMEM_BYTES>>>(x, nullptr, nullptr, w_fr, b_fr, out);

    // layer 0 fused: h0 = relu(bn(s)) + r0; t1 = fp16(h0 @ w_g1 + b)
    gemm_tc<HID, HID, false, true, true, true><<<dim3(ROWB, 1), 256, GEMM_SMEM_BYTES>>>(ps, pr, ph, w_g1, b_g1, pt16);

    // layer 1
    spmm_stats<<<dim3(8, GG), dim3(16, 16)>>>(pt16, ps);
    bn_finalize<<<1, HID>>>(gamma + 1 * HID, beta + 1 * HID);
    gemm_tc<HID, HID, false, true, true, true><<<dim3(ROWB, 1), 256, GEMM_SMEM_BYTES>>>(ps, ph, ph, w_g2, b_g2, pt16);

    // layer 2: h2 never materialized; out += h2 @ w_fc + b_fc
    spmm_stats<<<dim3(8, GG), dim3(16, 16)>>>(pt16, ps);
    bn_finalize<<<1, HID>>>(gamma + 2 * HID, beta + 2 * HID);
    gemm_tc<HID, OUTF, true, true, false, false><<<dim3(ROWB, 2), 256, GEMM_SMEM_BYTES>>>(ps, ph, nullptr, w_fc, b_fc, out);
}

// round 10
// speedup vs baseline: 1.2631x; 1.2631x over previous
#include <cuda_runtime.h>
#include <cuda_fp16.h>
#include <cstdint>

#define GG 512            // B*T graphs
#define NN 500            // nodes
#define FIN 96
#define HID 64
#define OUTF 96
#define ROWS (GG*NN)      // 256000
#define BN_EPS 1e-5f
#define NNZ_MAX (NN*NN)
#define SLICE 63          // rows per spmm block
#define ECAP 3072         // staged ecsr entries per block (24KB)

// ---------------- scratch (device globals; no allocation allowed) ----------------
__device__ __half2 g_t16[(long)ROWS*HID/2]; // GEMM output / SpMM input (fp16)
__device__ float g_s[(long)ROWS*HID];    // SpMM output
__device__ float g_h[(long)ROWS*HID];    // layer activations (residual chain)
__device__ float g_r[(long)ROWS*HID];    // layer-0 residual (x @ w_r0 + b_r0)
__device__ float g_dinv[NN];
__device__ int   g_cnt[NN];
__device__ int   g_rowptr[NN+1];
__device__ float2 g_ecsr[NNZ_MAX];       // packed (col-byte-offset-as-int-bits, val)
__device__ float g_sum[HID];
__device__ float g_sumsq[HID];
__device__ float g_scale[HID];
__device__ float g_shift[HID];

// ---------------- prep 1: degrees / dinv + per-row nnz counts ----------------
__global__ void prep_deg(const float* __restrict__ adj) {
    int m = blockIdx.x;
    int tid = threadIdx.x;
    float sum = 0.f; int cnt = 0;
    for (int n = tid; n < NN; n += blockDim.x) {
        float a = adj[m*NN + n];
        sum += a;
        cnt += (a != 0.f) ? 1 : 0;
    }
    __shared__ float ssum[4]; __shared__ int scnt[4];
    #pragma unroll
    for (int o = 16; o; o >>= 1) {
        sum += __shfl_down_sync(0xFFFFFFFFu, sum, o);
        cnt += __shfl_down_sync(0xFFFFFFFFu, cnt, o);
    }
    int w = tid >> 5;
    if ((tid & 31) == 0) { ssum[w] = sum; scnt[w] = cnt; }
    __syncthreads();
    if (tid == 0) {
        float s = ssum[0] + ssum[1] + ssum[2] + ssum[3];
        int c = scnt[0] + scnt[1] + scnt[2] + scnt[3];
        g_dinv[m] = rsqrtf(1.f + s);
        g_cnt[m] = c + 1;   // + diagonal
    }
    if (blockIdx.x == 0 && tid < HID) { g_sum[tid] = 0.f; g_sumsq[tid] = 0.f; }
}

// ---------------- prep 2: scan (redundant per block) + warp-parallel CSR fill ----
// grid (32, 512 threads = 16 warps). Every block redundantly scans the 500 counts
// in smem, then each warp fills one row via ballot-compaction: coalesced adj
// reads, deterministic ascending column order. Columns stored as BYTE OFFSETS
// (n * HID * 2) so the SpMM inner loop does pointer+offset adds, no IMAD.WIDE.
__global__ __launch_bounds__(512) void prep_scanfill(const float* __restrict__ adj) {
    __shared__ int sc[512];
    int tid = threadIdx.x;
    sc[tid] = (tid < NN) ? g_cnt[tid] : 0;
    __syncthreads();
    for (int off = 1; off < 512; off <<= 1) {
        int v = (tid >= off) ? sc[tid - off] : 0;
        __syncthreads();
        sc[tid] += v;
        __syncthreads();
    }
    if (blockIdx.x == 0) {
        if (tid < NN) g_rowptr[tid + 1] = sc[tid];
        if (tid == 0) g_rowptr[0] = 0;
    }
    int w = tid >> 5;
    int lane = tid & 31;
    int m = blockIdx.x * 16 + w;
    if (m >= NN) return;
    float dm = g_dinv[m];
    int p = (m == 0) ? 0 : sc[m - 1];
    for (int n0 = 0; n0 < 512; n0 += 32) {
        int n = n0 + lane;
        bool valid = n < NN;
        float a = valid ? adj[m*NN + n] : 0.f;
        bool nz = valid && (a != 0.f || n == m);
        float val = (n == m) ? dm * dm : dm * a * (valid ? g_dinv[valid ? n : 0] : 0.f);
        unsigned mask = __ballot_sync(0xFFFFFFFFu, nz);
        int pos = p + __popc(mask & ((1u << lane) - 1u));
        if (nz) g_ecsr[pos] = make_float2(__int_as_float(n * (HID * 2)), val);
        p += __popc(mask);
    }
}

// ---------------- tensor-core GEMM: fp16 2-way split, m16n8k16, fp32 accum ------
// C[row,c] = sum_f A'[row,f]*B[f,c] + bias[c]   (optional += existing C)
// A = Ahi + Alo (fp16 each, ~22 mantissa bits covered); 3 MMAs: hh + hl + lh.
// FUSE: A'[row,f] = max(A[row,f]*scale[f]+shift[f], 0) + R[row,f]; opt. write Hout.
// OUT_HALF: result stored as __half2 (t feeding the SpMM gather path).

__device__ __forceinline__ uint32_t h2u(__half2 h) { return *(uint32_t*)&h; }

__device__ __forceinline__ void f16_split2(float a, float b, uint32_t& hi, uint32_t& lo) {
    __half2 h = __floats2half2_rn(a, b);
    float2 back = __half22float2(h);
    __half2 l = __floats2half2_rn(a - back.x, b - back.y);
    hi = h2u(h); lo = h2u(l);
}

__device__ __forceinline__ void mma_f16(float* c, const uint32_t* a, const uint32_t* b) {
    asm volatile(
        "mma.sync.aligned.m16n8k16.row.col.f32.f16.f16.f32 "
        "{%0,%1,%2,%3}, {%4,%5,%6,%7}, {%8,%9}, {%0,%1,%2,%3};\n"
        : "+f"(c[0]), "+f"(c[1]), "+f"(c[2]), "+f"(c[3])
        : "r"(a[0]), "r"(a[1]), "r"(a[2]), "r"(a[3]), "r"(b[0]), "r"(b[1]));
}

template<int K, int C, bool ACCUM, bool FUSE, bool WRITE_H, bool OUT_HALF>
__global__ __launch_bounds__(256) void gemm_tc(
    const float* __restrict__ A, const float* __restrict__ R, float* __restrict__ Hout,
    const float* __restrict__ Bw, const float* __restrict__ bias, void* __restrict__ Cout)
{
    // half2 planes; index [row][kk] where kk packs k-pair (2kk, 2kk+1)
    __shared__ uint32_t AsH[128][20], AsL[128][20];   // stride 20 -> conflict-free frags
    __shared__ uint32_t BsH[16][72],  BsL[16][72];    // stride 72 -> conflict-free frags
    __shared__ float s_scale[HID], s_shift[HID];

    const int tid = threadIdx.x;
    const int wid = tid >> 5;
    const int lane = tid & 31;
    const int g  = lane >> 2;       // 0..7
    const int t4 = lane & 3;        // 0..3
    const int warp_m = wid >> 1;    // 0..3
    const int warp_n = wid & 1;     // 0..1

    const long row0 = (long)blockIdx.x * 128;
    const int col0 = blockIdx.y * 64;

    if (FUSE) {
        if (tid < HID) s_scale[tid] = g_scale[tid];
        else if (tid < 2*HID) s_shift[tid - HID] = g_shift[tid - HID];
        __syncthreads();
    }

    float acc[2][4][4];
    #pragma unroll
    for (int mt = 0; mt < 2; mt++)
        #pragma unroll
        for (int nt = 0; nt < 4; nt++)
            #pragma unroll
            for (int q = 0; q < 4; q++) acc[mt][nt][q] = 0.f;

    for (int k0 = 0; k0 < K; k0 += 32) {
        // --- stage A tile: 128 rows x 32 k; split to fp16 hi/lo half2 pairs ---
        #pragma unroll
        for (int i = 0; i < 4; i++) {
            int idx = tid + i * 256;
            int r = idx >> 3;
            int q = idx & 7;               // float4 index: k = q*4 .. q*4+3
            long off = (row0 + r) * K + (k0 + q * 4);
            float4 v = *(const float4*)(A + off);
            if (FUSE) {
                int kc = k0 + q * 4;
                float4 rv = *(const float4*)(R + off);
                v.x = fmaxf(v.x * s_scale[kc+0] + s_shift[kc+0], 0.f) + rv.x;
                v.y = fmaxf(v.y * s_scale[kc+1] + s_shift[kc+1], 0.f) + rv.y;
                v.z = fmaxf(v.z * s_scale[kc+2] + s_shift[kc+2], 0.f) + rv.z;
                v.w = fmaxf(v.w * s_scale[kc+3] + s_shift[kc+3], 0.f) + rv.w;
                if (WRITE_H) *(float4*)(Hout + off) = v;
            }
            uint32_t h01, l01, h23, l23;
            f16_split2(v.x, v.y, h01, l01);
            f16_split2(v.z, v.w, h23, l23);
            *(uint2*)&AsH[r][q*2] = make_uint2(h01, h23);
            *(uint2*)&AsL[r][q*2] = make_uint2(l01, l23);
        }
        // --- stage B tile: 32 k x 64 cols; pack k-pairs per column ---
        {
            int kk = tid >> 4;             // 0..15
            int cq = tid & 15;             // column quad
            int c = col0 + cq * 4;
            float4 v0 = make_float4(0.f,0.f,0.f,0.f);
            float4 v1 = make_float4(0.f,0.f,0.f,0.f);
            if ((C & 63) == 0 || c < C) {
                v0 = *(const float4*)(Bw + (k0 + 2*kk    ) * C + c);
                v1 = *(const float4*)(Bw + (k0 + 2*kk + 1) * C + c);
            }
            uint32_t h, l;
            f16_split2(v0.x, v1.x, h, l); BsH[kk][cq*4+0] = h; BsL[kk][cq*4+0] = l;
            f16_split2(v0.y, v1.y, h, l); BsH[kk][cq*4+1] = h; BsL[kk][cq*4+1] = l;
            f16_split2(v0.z, v1.z, h, l); BsH[kk][cq*4+2] = h; BsL[kk][cq*4+2] = l;
            f16_split2(v0.w, v1.w, h, l); BsH[kk][cq*4+3] = h; BsL[kk][cq*4+3] = l;
        }
        __syncthreads();

        #pragma unroll
        for (int s = 0; s < 2; s++) {      // two k16 steps per 32-chunk
            uint32_t ah[2][4], al[2][4];
            #pragma unroll
            for (int mt = 0; mt < 2; mt++) {
                int r = warp_m * 32 + mt * 16 + g;
                int kc = s * 8 + t4;
                ah[mt][0] = AsH[r][kc];     al[mt][0] = AsL[r][kc];
                ah[mt][1] = AsH[r+8][kc];   al[mt][1] = AsL[r+8][kc];
                ah[mt][2] = AsH[r][kc+4];   al[mt][2] = AsL[r][kc+4];
                ah[mt][3] = AsH[r+8][kc+4]; al[mt][3] = AsL[r+8][kc+4];
            }
            uint32_t bh[4][2], bl[4][2];
            #pragma unroll
            for (int nt = 0; nt < 4; nt++) {
                int nb = warp_n * 32 + nt * 8 + g;
                int kr = s * 8 + t4;
                bh[nt][0] = BsH[kr][nb];    bl[nt][0] = BsL[kr][nb];
                bh[nt][1] = BsH[kr+4][nb];  bl[nt][1] = BsL[kr+4][nb];
            }
            #pragma unroll
            for (int mt = 0; mt < 2; mt++)
                #pragma unroll
                for (int nt = 0; nt < 4; nt++) {
                    mma_f16(acc[mt][nt], ah[mt], bh[nt]);
                    mma_f16(acc[mt][nt], ah[mt], bl[nt]);
                    mma_f16(acc[mt][nt], al[mt], bh[nt]);
                }
        }
        __syncthreads();
    }

    // --- epilogue (c layout identical to m16n8k8: (g,2t4),(g,2t4+1),(g+8,...)) ---
    #pragma unroll
    for (int mt = 0; mt < 2; mt++) {
        long rowa = row0 + warp_m * 32 + mt * 16 + g;
        long rowb = rowa + 8;
        #pragma unroll
        for (int nt = 0; nt < 4; nt++) {
            int col = col0 + warp_n * 32 + nt * 8 + 2 * t4;
            if ((C & 63) == 0 || col < C) {
                float bx = bias[col];
                float by = bias[col + 1];
                float2 v0 = make_float2(acc[mt][nt][0] + bx, acc[mt][nt][1] + by);
                float2 v1 = make_float2(acc[mt][nt][2] + bx, acc[mt][nt][3] + by);
                if (OUT_HALF) {
                    __half2* o = (__half2*)Cout;
                    o[(rowa * C + col) >> 1] = __floats2half2_rn(v0.x, v0.y);
                    o[(rowb * C + col) >> 1] = __floats2half2_rn(v1.x, v1.y);
                } else {
                    float* d0 = (float*)Cout + rowa * C + col;
                    float* d1 = (float*)Cout + rowb * C + col;
                    if (ACCUM) {
                        float2 o0 = *(const float2*)d0;
                        float2 o1 = *(const float2*)d1;
                        v0.x += o0.x; v0.y += o0.y;
                        v1.x += o1.x; v1.y += o1.y;
                    }
                    *(float2*)d0 = v0;
                    *(float2*)d1 = v1;
                }
            }
        }
    }
}

// ---------------- SpMM (s = a_hat @ t per graph) + BN stats partials ----------------
// grid (8, GG), blockDim (16,16): 63-row slices; ecsr slice staged in smem.
// CSR "col" is a BYTE OFFSET into the fp16 T row array: addr = base + off.
// Each thread owns 4 fp16 channels = 8 bytes (cx*8); 16 threads = one 128B row.
__global__ __launch_bounds__(256) void spmm_stats(
    const __half2* __restrict__ T2, float* __restrict__ S)
{
    __shared__ float2 se[ECAP];
    __shared__ float red[16][64];

    int g = blockIdx.y;
    int m0 = blockIdx.x * SLICE;
    int mend = min(m0 + SLICE, NN);
    int cx = threadIdx.x;
    int c4 = cx * 4;
    int yr = threadIdx.y;
    int tid = yr * 16 + cx;
    const char* base = (const char*)T2 + (long)g * (NN * HID * 2) + cx * 8;
    float* sg = S + (long)g * NN * HID;

    int bse = g_rowptr[m0];
    int cnt = g_rowptr[mend] - bse;
    int scount = min(cnt, ECAP);
    for (int i = tid; i < scount; i += 256) se[i] = g_ecsr[bse + i];
    __syncthreads();

    float lsum[4] = {0,0,0,0}, lsq[4] = {0,0,0,0};

    for (int m = m0 + yr; m < mend; m += 16) {
        int jb = g_rowptr[m] - bse, je = g_rowptr[m + 1] - bse;
        float4 a0 = make_float4(0.f, 0.f, 0.f, 0.f);
        float4 a1 = make_float4(0.f, 0.f, 0.f, 0.f);
        if (je <= ECAP) {
            int j = jb;
            for (; j + 3 < je; j += 4) {
                float2 cv0 = se[j],     cv1 = se[j + 1];
                float2 cv2 = se[j + 2], cv3 = se[j + 3];
                float w0 = cv0.y, w1 = cv1.y, w2 = cv2.y, w3 = cv3.y;
                uint2 r0 = *(const uint2*)(base + __float_as_int(cv0.x));
                uint2 r1 = *(const uint2*)(base + __float_as_int(cv1.x));
                uint2 r2 = *(const uint2*)(base + __float_as_int(cv2.x));
                uint2 r3 = *(const uint2*)(base + __float_as_int(cv3.x));
                float2 t0a = __half22float2(*(__half2*)&r0.x), t0b = __half22float2(*(__half2*)&r0.y);
                float2 t1a = __half22float2(*(__half2*)&r1.x), t1b = __half22float2(*(__half2*)&r1.y);
                float2 t2a = __half22float2(*(__half2*)&r2.x), t2b = __half22float2(*(__half2*)&r2.y);
                float2 t3a = __half22float2(*(__half2*)&r3.x), t3b = __half22float2(*(__half2*)&r3.y);
                a0.x += w0 * t0a.x + w1 * t1a.x;  a1.x += w2 * t2a.x + w3 * t3a.x;
                a0.y += w0 * t0a.y + w1 * t1a.y;  a1.y += w2 * t2a.y + w3 * t3a.y;
                a0.z += w0 * t0b.x + w1 * t1b.x;  a1.z += w2 * t2b.x + w3 * t3b.x;
                a0.w += w0 * t0b.y + w1 * t1b.y;  a1.w += w2 * t2b.y + w3 * t3b.y;
            }
            for (; j < je; j++) {
                float2 cv = se[j];
                float w = cv.y;
                uint2 r = *(const uint2*)(base + __float_as_int(cv.x));
                float2 ta = __half22float2(*(__half2*)&r.x), tb = __half22float2(*(__half2*)&r.y);
                a0.x += w * ta.x; a0.y += w * ta.y;
                a0.z += w * tb.x; a0.w += w * tb.y;
            }
        } else {
            for (int j = jb; j < je; j++) {   // statistically-never fallback
                float2 cv = g_ecsr[bse + j];
                float w = cv.y;
                uint2 r = *(const uint2*)(base + __float_as_int(cv.x));
                float2 ta = __half22float2(*(__half2*)&r.x), tb = __half22float2(*(__half2*)&r.y);
                a0.x += w * ta.x; a0.y += w * ta.y;
                a0.z += w * tb.x; a0.w += w * tb.y;
            }
        }
        float4 acc = make_float4(a0.x + a1.x, a0.y + a1.y, a0.z + a1.z, a0.w + a1.w);
        *(float4*)(sg + m * HID + c4) = acc;
        lsum[0] += acc.x; lsum[1] += acc.y; lsum[2] += acc.z; lsum[3] += acc.w;
        lsq[0] += acc.x * acc.x; lsq[1] += acc.y * acc.y;
        lsq[2] += acc.z * acc.z; lsq[3] += acc.w * acc.w;
    }

    #pragma unroll
    for (int k = 0; k < 4; k++) red[yr][c4 + k] = lsum[k];
    __syncthreads();
    for (int off = 8; off >= 1; off >>= 1) {
        if (yr < off)
            #pragma unroll
            for (int k = 0; k < 4; k++) red[yr][c4 + k] += red[yr + off][c4 + k];
        __syncthreads();
    }
    if (yr == 0)
        #pragma unroll
        for (int k = 0; k < 4; k++) atomicAdd(&g_sum[c4 + k], red[0][c4 + k]);
    __syncthreads();
    #pragma unroll
    for (int k = 0; k < 4; k++) red[yr][c4 + k] = lsq[k];
    __syncthreads();
    for (int off = 8; off >= 1; off >>= 1) {
        if (yr < off)
            #pragma unroll
            for (int k = 0; k < 4; k++) red[yr][c4 + k] += red[yr + off][c4 + k];
        __syncthreads();
    }
    if (yr == 0)
        #pragma unroll
        for (int k = 0; k < 4; k++) atomicAdd(&g_sumsq[c4 + k], red[0][c4 + k]);
}

// ---------------- BN finalize ----------------
__global__ void bn_finalize(const float* __restrict__ gamma, const float* __restrict__ beta) {
    int c = threadIdx.x;
    float s = g_sum[c], q = g_sumsq[c];
    const float inv = 1.f / (float)ROWS;
    float mean = s * inv;
    float var = q * inv - mean * mean;
    float rstd = rsqrtf(var + BN_EPS);
    float a = rstd * gamma[c];
    g_scale[c] = a;
    g_shift[c] = beta[c] - mean * a;
    g_sum[c] = 0.f; g_sumsq[c] = 0.f;
}

// ---------------- launch ----------------
extern "C" void kernel_launch(void* const* d_in, const int* in_sizes, int n_in,
                              void* d_out, int out_size)
{
    const float* x     = (const float*)d_in[0];
    const float* adj   = (const float*)d_in[1];
    const float* w_g0  = (const float*)d_in[2];
    const float* b_g0  = (const float*)d_in[3];
    const float* w_g1  = (const float*)d_in[4];
    const float* b_g1  = (const float*)d_in[5];
    const float* w_g2  = (const float*)d_in[6];
    const float* b_g2  = (const float*)d_in[7];
    const float* gamma = (const float*)d_in[8];
    const float* beta  = (const float*)d_in[9];
    const float* w_r0  = (const float*)d_in[10];
    const float* b_r0  = (const float*)d_in[11];
    const float* w_fc  = (const float*)d_in[12];
    const float* b_fc  = (const float*)d_in[13];
    const float* w_fr  = (const float*)d_in[14];
    const float* b_fr  = (const float*)d_in[15];
    float* out = (float*)d_out;

    __half2 *pt16;
    float *ps, *ph, *pr;
    cudaGetSymbolAddress((void**)&pt16, g_t16);
    cudaGetSymbolAddress((void**)&ps, g_s);
    cudaGetSymbolAddress((void**)&ph, g_h);
    cudaGetSymbolAddress((void**)&pr, g_r);

    const int ROWB = ROWS / 128;               // 2000

    // #0: t0 = fp16(x@w_g0+b)
    gemm_tc<FIN, HID, false, false, false, true><<<dim3(ROWB, 1), 256>>>(x, nullptr, nullptr, w_g0, b_g0, pt16);

    // #1,#2: CSR of a_hat (deterministic, warp-ballot fill)
    prep_deg<<<NN, 128>>>(adj);
    prep_scanfill<<<32, 512>>>(adj);

    // #3: layer-0 SpMM  ← ncu capture slot
    spmm_stats<<<dim3(8, GG), dim3(16, 16)>>>(pt16, ps);
    bn_finalize<<<1, HID>>>(gamma + 0 * HID, beta + 0 * HID);

    // remaining input GEMMs
    gemm_tc<FIN, HID, false, false, false, false><<<dim3(ROWB, 1), 256>>>(x, nullptr, nullptr, w_r0, b_r0, pr);
    gemm_tc<FIN, OUTF, false, false, false, false><<<dim3(ROWB, 2), 256>>>(x, nullptr, nullptr, w_fr, b_fr, out);

    // layer 0 fused: h0 = relu(bn(s)) + r0; t1 = fp16(h0 @ w_g1 + b)
    gemm_tc<HID, HID, false, true, true, true><<<dim3(ROWB, 1), 256>>>(ps, pr, ph, w_g1, b_g1, pt16);

    // layer 1
    spmm_stats<<<dim3(8, GG), dim3(16, 16)>>>(pt16, ps);
    bn_finalize<<<1, HID>>>(gamma + 1 * HID, beta + 1 * HID);
    gemm_tc<HID, HID, false, true, true, true><<<dim3(ROWB, 1), 256>>>(ps, ph, ph, w_g2, b_g2, pt16);

    // layer 2: h2 never materialized; out += h2 @ w_fc + b_fc
    spmm_stats<<<dim3(8, GG), dim3(16, 16)>>>(pt16, ps);
    bn_finalize<<<1, HID>>>(gamma + 2 * HID, beta + 2 * HID);
    gemm_tc<HID, OUTF, true, true, false, false><<<dim3(ROWB, 2), 256>>>(ps, ph, nullptr, w_fc, b_fc, out);
}

// round 11
// speedup vs baseline: 1.4981x; 1.1860x over previous
#include <cuda_runtime.h>
#include <cuda_fp16.h>
#include <cstdint>

#define GG 512            // B*T graphs
#define NN 500            // nodes
#define NP 512            // padded node count (MMA K/M)
#define FIN 96
#define HID 64
#define OUTF 96
#define ROWS (GG*NN)      // 256000
#define BN_EPS 1e-5f

// ---------------- scratch (device globals; no allocation allowed) ----------------
// g_t16 has 16 rows of slack: padded-K B-reads for the last graph land here.
// Device globals are zero-initialized and the slack is never written -> reads 0.
__device__ __half2 g_t16[((long)ROWS + 16)*HID/2]; // GEMM output / SpMM input (fp16)
__device__ __half  g_ahat[NP*NP];        // dense fp16 a_hat, zero-padded to 512x512
__device__ float g_s[(long)ROWS*HID];    // SpMM output
__device__ float g_h[(long)ROWS*HID];    // layer activations (residual chain)
__device__ float g_r[(long)ROWS*HID];    // layer-0 residual (x @ w_r0 + b_r0)
__device__ float g_dinv[NN];
__device__ float g_sum[HID];
__device__ float g_sumsq[HID];
__device__ float g_scale[HID];
__device__ float g_shift[HID];

// ---------------- prep 1: degrees -> dinv ----------------
__global__ void prep_deg(const float* __restrict__ adj) {
    int m = blockIdx.x;
    int tid = threadIdx.x;
    float sum = 0.f;
    for (int n = tid; n < NN; n += blockDim.x) sum += adj[m*NN + n];
    __shared__ float ssum[4];
    #pragma unroll
    for (int o = 16; o; o >>= 1) sum += __shfl_down_sync(0xFFFFFFFFu, sum, o);
    int w = tid >> 5;
    if ((tid & 31) == 0) ssum[w] = sum;
    __syncthreads();
    if (tid == 0)
        g_dinv[m] = rsqrtf(1.f + ssum[0] + ssum[1] + ssum[2] + ssum[3]);
    if (blockIdx.x == 0 && tid < HID) { g_sum[tid] = 0.f; g_sumsq[tid] = 0.f; }
}

// ---------------- prep 2: dense fp16 a_hat (zero-padded) ----------------
__global__ void prep_fill_dense(const float* __restrict__ adj) {
    int m = blockIdx.x;                       // 0..511
    float dm = (m < NN) ? g_dinv[m] : 0.f;
    for (int n = threadIdx.x; n < NP; n += blockDim.x) {
        float v = 0.f;
        if (m < NN && n < NN)
            v = (n == m) ? dm * dm : adj[m*NN + n] * dm * g_dinv[n];
        g_ahat[m*NP + n] = __float2half(v);
    }
}

// ---------------- fp16 MMA helpers ----------------
__device__ __forceinline__ uint32_t h2u(__half2 h) { return *(uint32_t*)&h; }

__device__ __forceinline__ void f16_split2(float a, float b, uint32_t& hi, uint32_t& lo) {
    __half2 h = __floats2half2_rn(a, b);
    float2 back = __half22float2(h);
    __half2 l = __floats2half2_rn(a - back.x, b - back.y);
    hi = h2u(h); lo = h2u(l);
}

__device__ __forceinline__ void mma_f16(float* c, const uint32_t* a, const uint32_t* b) {
    asm volatile(
        "mma.sync.aligned.m16n8k16.row.col.f32.f16.f16.f32 "
        "{%0,%1,%2,%3}, {%4,%5,%6,%7}, {%8,%9}, {%0,%1,%2,%3};\n"
        : "+f"(c[0]), "+f"(c[1]), "+f"(c[2]), "+f"(c[3])
        : "r"(a[0]), "r"(a[1]), "r"(a[2]), "r"(a[3]), "r"(b[0]), "r"(b[1]));
}

// ---------------- SpMM as batched dense MMA + fused BN stats ----------------
// grid (4, GG): 128-row tile x one graph. 256 threads = 8 warps (4m x 2n).
// S[g] = Ahat(512x512, fp16, zero-padded) @ T[g](512x64 fp16, padded reads are 0).
// Both operands already fp16 in memory -> staging is a pure copy.
__global__ __launch_bounds__(256) void spmm_mma(
    const __half2* __restrict__ T2, float* __restrict__ S)
{
    __shared__ uint32_t As[128][20];   // [row][kpair], stride 20 -> conflict-free frags
    __shared__ uint32_t Bs[16][72];    // [kpair][col],  stride 72 -> conflict-free frags
    __shared__ float ssum[8][32], ssq[8][32];

    const int tid = threadIdx.x;
    const int wid = tid >> 5;
    const int lane = tid & 31;
    const int g  = lane >> 2;
    const int t4 = lane & 3;
    const int warp_m = wid >> 1;
    const int warp_n = wid & 1;

    const int gph = blockIdx.y;
    const int row0 = blockIdx.x * 128;               // graph-local row
    const __half* Tg = (const __half*)T2 + (long)gph * NN * HID;
    float* Sg = S + (long)gph * NN * HID;

    float acc[2][4][4];
    #pragma unroll
    for (int mt = 0; mt < 2; mt++)
        #pragma unroll
        for (int nt = 0; nt < 4; nt++)
            #pragma unroll
            for (int q = 0; q < 4; q++) acc[mt][nt][q] = 0.f;

    for (int k0 = 0; k0 < NP; k0 += 32) {
        // stage A: 128 rows x 32 k (pure fp16 copy; 2 x uint4 per thread)
        #pragma unroll
        for (int i = 0; i < 2; i++) {
            int idx = tid + i * 256;       // 512 uint4 tasks
            int r = idx >> 2;
            int q = idx & 3;
            uint4 v = *(const uint4*)(g_ahat + (long)(row0 + r) * NP + k0 + q * 8);
            *(uint4*)&As[r][q * 4] = v;
        }
        // stage B: 32 k x 64 ch, repacked to (k,k+1) half2 per column
        #pragma unroll
        for (int i = 0; i < 2; i++) {
            int idx = tid + i * 256;       // 512 tasks: kp 0..15 x cpair 0..31
            int kp = idx >> 5;
            int cp = idx & 31;
            long k = k0 + 2 * kp;
            __half2 l2 = *(const __half2*)(Tg + k * HID + cp * 2);
            __half2 h2v = *(const __half2*)(Tg + (k + 1) * HID + cp * 2);
            Bs[kp][cp*2]     = h2u(__lows2half2(l2, h2v));
            Bs[kp][cp*2 + 1] = h2u(__highs2half2(l2, h2v));
        }
        __syncthreads();

        #pragma unroll
        for (int s = 0; s < 2; s++) {
            uint32_t a[2][4], b[4][2];
            #pragma unroll
            for (int mt = 0; mt < 2; mt++) {
                int r = warp_m * 32 + mt * 16 + g;
                int kc = s * 8 + t4;
                a[mt][0] = As[r][kc];     a[mt][1] = As[r+8][kc];
                a[mt][2] = As[r][kc+4];   a[mt][3] = As[r+8][kc+4];
            }
            #pragma unroll
            for (int nt = 0; nt < 4; nt++) {
                int nb = warp_n * 32 + nt * 8 + g;
                int kr = s * 8 + t4;
                b[nt][0] = Bs[kr][nb];    b[nt][1] = Bs[kr+4][nb];
            }
            #pragma unroll
            for (int mt = 0; mt < 2; mt++)
                #pragma unroll
                for (int nt = 0; nt < 4; nt++)
                    mma_f16(acc[mt][nt], a[mt], b[nt]);
        }
        __syncthreads();
    }

    // --- epilogue: store S (guard row < 500) ---
    #pragma unroll
    for (int mt = 0; mt < 2; mt++) {
        int rowa = row0 + warp_m * 32 + mt * 16 + g;
        int rowb = rowa + 8;
        #pragma unroll
        for (int nt = 0; nt < 4; nt++) {
            int col = warp_n * 32 + nt * 8 + 2 * t4;
            if (rowa < NN)
                *(float2*)(Sg + (long)rowa * HID + col) = make_float2(acc[mt][nt][0], acc[mt][nt][1]);
            if (rowb < NN)
                *(float2*)(Sg + (long)rowb * HID + col) = make_float2(acc[mt][nt][2], acc[mt][nt][3]);
        }
    }

    // --- BN stats: rows >= 500 are exactly zero (zero A rows), contribute nothing ---
    float ls[8], lq[8];
    #pragma unroll
    for (int nt = 0; nt < 4; nt++)
        #pragma unroll
        for (int b = 0; b < 2; b++) {
            float v0 = acc[0][nt][b], v1 = acc[0][nt][b+2];
            float v2 = acc[1][nt][b], v3 = acc[1][nt][b+2];
            ls[nt*2+b] = v0 + v1 + v2 + v3;
            lq[nt*2+b] = v0*v0 + v1*v1 + v2*v2 + v3*v3;
        }
    #pragma unroll
    for (int i = 0; i < 8; i++) {
        #pragma unroll
        for (int off = 4; off <= 16; off <<= 1) {
            ls[i] += __shfl_xor_sync(0xFFFFFFFFu, ls[i], off);
            lq[i] += __shfl_xor_sync(0xFFFFFFFFu, lq[i], off);
        }
    }
    if (lane < 4) {
        #pragma unroll
        for (int nt = 0; nt < 4; nt++)
            #pragma unroll
            for (int b = 0; b < 2; b++) {
                ssum[wid][nt*8 + 2*lane + b] = ls[nt*2+b];
                ssq [wid][nt*8 + 2*lane + b] = lq[nt*2+b];
            }
    }
    __syncthreads();
    if (tid < 128) {
        int col = tid & 63;
        int wn = col >> 5, lc = col & 31;
        bool isq = tid >= 64;
        float t = 0.f;
        #pragma unroll
        for (int w = 0; w < 4; w++) {
            int wd = w * 2 + wn;
            t += isq ? ssq[wd][lc] : ssum[wd][lc];
        }
        atomicAdd(isq ? &g_sumsq[col] : &g_sum[col], t);
    }
}

// ---------------- tensor-core GEMM: fp16 2-way split, m16n8k16, fp32 accum ------
// (unchanged from R10 — validated at rel_err 1.42e-4)
template<int K, int C, bool ACCUM, bool FUSE, bool WRITE_H, bool OUT_HALF>
__global__ __launch_bounds__(256) void gemm_tc(
    const float* __restrict__ A, const float* __restrict__ R, float* __restrict__ Hout,
    const float* __restrict__ Bw, const float* __restrict__ bias, void* __restrict__ Cout)
{
    __shared__ uint32_t AsH[128][20], AsL[128][20];
    __shared__ uint32_t BsH[16][72],  BsL[16][72];
    __shared__ float s_scale[HID], s_shift[HID];

    const int tid = threadIdx.x;
    const int wid = tid >> 5;
    const int lane = tid & 31;
    const int g  = lane >> 2;
    const int t4 = lane & 3;
    const int warp_m = wid >> 1;
    const int warp_n = wid & 1;

    const long row0 = (long)blockIdx.x * 128;
    const int col0 = blockIdx.y * 64;

    if (FUSE) {
        if (tid < HID) s_scale[tid] = g_scale[tid];
        else if (tid < 2*HID) s_shift[tid - HID] = g_shift[tid - HID];
        __syncthreads();
    }

    float acc[2][4][4];
    #pragma unroll
    for (int mt = 0; mt < 2; mt++)
        #pragma unroll
        for (int nt = 0; nt < 4; nt++)
            #pragma unroll
            for (int q = 0; q < 4; q++) acc[mt][nt][q] = 0.f;

    for (int k0 = 0; k0 < K; k0 += 32) {
        #pragma unroll
        for (int i = 0; i < 4; i++) {
            int idx = tid + i * 256;
            int r = idx >> 3;
            int q = idx & 7;
            long off = (row0 + r) * K + (k0 + q * 4);
            float4 v = *(const float4*)(A + off);
            if (FUSE) {
                int kc = k0 + q * 4;
                float4 rv = *(const float4*)(R + off);
                v.x = fmaxf(v.x * s_scale[kc+0] + s_shift[kc+0], 0.f) + rv.x;
                v.y = fmaxf(v.y * s_scale[kc+1] + s_shift[kc+1], 0.f) + rv.y;
                v.z = fmaxf(v.z * s_scale[kc+2] + s_shift[kc+2], 0.f) + rv.z;
                v.w = fmaxf(v.w * s_scale[kc+3] + s_shift[kc+3], 0.f) + rv.w;
                if (WRITE_H) *(float4*)(Hout + off) = v;
            }
            uint32_t h01, l01, h23, l23;
            f16_split2(v.x, v.y, h01, l01);
            f16_split2(v.z, v.w, h23, l23);
            *(uint2*)&AsH[r][q*2] = make_uint2(h01, h23);
            *(uint2*)&AsL[r][q*2] = make_uint2(l01, l23);
        }
        {
            int kk = tid >> 4;
            int cq = tid & 15;
            int c = col0 + cq * 4;
            float4 v0 = make_float4(0.f,0.f,0.f,0.f);
            float4 v1 = make_float4(0.f,0.f,0.f,0.f);
            if ((C & 63) == 0 || c < C) {
                v0 = *(const float4*)(Bw + (k0 + 2*kk    ) * C + c);
                v1 = *(const float4*)(Bw + (k0 + 2*kk + 1) * C + c);
            }
            uint32_t h, l;
            f16_split2(v0.x, v1.x, h, l); BsH[kk][cq*4+0] = h; BsL[kk][cq*4+0] = l;
            f16_split2(v0.y, v1.y, h, l); BsH[kk][cq*4+1] = h; BsL[kk][cq*4+1] = l;
            f16_split2(v0.z, v1.z, h, l); BsH[kk][cq*4+2] = h; BsL[kk][cq*4+2] = l;
            f16_split2(v0.w, v1.w, h, l); BsH[kk][cq*4+3] = h; BsL[kk][cq*4+3] = l;
        }
        __syncthreads();

        #pragma unroll
        for (int s = 0; s < 2; s++) {
            uint32_t ah[2][4], al[2][4];
            #pragma unroll
            for (int mt = 0; mt < 2; mt++) {
                int r = warp_m * 32 + mt * 16 + g;
                int kc = s * 8 + t4;
                ah[mt][0] = AsH[r][kc];     al[mt][0] = AsL[r][kc];
                ah[mt][1] = AsH[r+8][kc];   al[mt][1] = AsL[r+8][kc];
                ah[mt][2] = AsH[r][kc+4];   al[mt][2] = AsL[r][kc+4];
                ah[mt][3] = AsH[r+8][kc+4]; al[mt][3] = AsL[r+8][kc+4];
            }
            uint32_t bh[4][2], bl[4][2];
            #pragma unroll
            for (int nt = 0; nt < 4; nt++) {
                int nb = warp_n * 32 + nt * 8 + g;
                int kr = s * 8 + t4;
                bh[nt][0] = BsH[kr][nb];    bl[nt][0] = BsL[kr][nb];
                bh[nt][1] = BsH[kr+4][nb];  bl[nt][1] = BsL[kr+4][nb];
            }
            #pragma unroll
            for (int mt = 0; mt < 2; mt++)
                #pragma unroll
                for (int nt = 0; nt < 4; nt++) {
                    mma_f16(acc[mt][nt], ah[mt], bh[nt]);
                    mma_f16(acc[mt][nt], ah[mt], bl[nt]);
                    mma_f16(acc[mt][nt], al[mt], bh[nt]);
                }
        }
        __syncthreads();
    }

    #pragma unroll
    for (int mt = 0; mt < 2; mt++) {
        long rowa = row0 + warp_m * 32 + mt * 16 + g;
        long rowb = rowa + 8;
        #pragma unroll
        for (int nt = 0; nt < 4; nt++) {
            int col = col0 + warp_n * 32 + nt * 8 + 2 * t4;
            if ((C & 63) == 0 || col < C) {
                float bx = bias[col];
                float by = bias[col + 1];
                float2 v0 = make_float2(acc[mt][nt][0] + bx, acc[mt][nt][1] + by);
                float2 v1 = make_float2(acc[mt][nt][2] + bx, acc[mt][nt][3] + by);
                if (OUT_HALF) {
                    __half2* o = (__half2*)Cout;
                    o[(rowa * C + col) >> 1] = __floats2half2_rn(v0.x, v0.y);
                    o[(rowb * C + col) >> 1] = __floats2half2_rn(v1.x, v1.y);
                } else {
                    float* d0 = (float*)Cout + rowa * C + col;
                    float* d1 = (float*)Cout + rowb * C + col;
                    if (ACCUM) {
                        float2 o0 = *(const float2*)d0;
                        float2 o1 = *(const float2*)d1;
                        v0.x += o0.x; v0.y += o0.y;
                        v1.x += o1.x; v1.y += o1.y;
                    }
                    *(float2*)d0 = v0;
                    *(float2*)d1 = v1;
                }
            }
        }
    }
}

// ---------------- BN finalize ----------------
__global__ void bn_finalize(const float* __restrict__ gamma, const float* __restrict__ beta) {
    int c = threadIdx.x;
    float s = g_sum[c], q = g_sumsq[c];
    const float inv = 1.f / (float)ROWS;
    float mean = s * inv;
    float var = q * inv - mean * mean;
    float rstd = rsqrtf(var + BN_EPS);
    float a = rstd * gamma[c];
    g_scale[c] = a;
    g_shift[c] = beta[c] - mean * a;
    g_sum[c] = 0.f; g_sumsq[c] = 0.f;
}

// ---------------- launch ----------------
extern "C" void kernel_launch(void* const* d_in, const int* in_sizes, int n_in,
                              void* d_out, int out_size)
{
    const float* x     = (const float*)d_in[0];
    const float* adj   = (const float*)d_in[1];
    const float* w_g0  = (const float*)d_in[2];
    const float* b_g0  = (const float*)d_in[3];
    const float* w_g1  = (const float*)d_in[4];
    const float* b_g1  = (const float*)d_in[5];
    const float* w_g2  = (const float*)d_in[6];
    const float* b_g2  = (const float*)d_in[7];
    const float* gamma = (const float*)d_in[8];
    const float* beta  = (const float*)d_in[9];
    const float* w_r0  = (const float*)d_in[10];
    const float* b_r0  = (const float*)d_in[11];
    const float* w_fc  = (const float*)d_in[12];
    const float* b_fc  = (const float*)d_in[13];
    const float* w_fr  = (const float*)d_in[14];
    const float* b_fr  = (const float*)d_in[15];
    float* out = (float*)d_out;

    __half2 *pt16;
    float *ps, *ph, *pr;
    cudaGetSymbolAddress((void**)&pt16, g_t16);
    cudaGetSymbolAddress((void**)&ps, g_s);
    cudaGetSymbolAddress((void**)&ph, g_h);
    cudaGetSymbolAddress((void**)&pr, g_r);

    const int ROWB = ROWS / 128;               // 2000

    // #0: t0 = fp16(x@w_g0+b)
    gemm_tc<FIN, HID, false, false, false, true><<<dim3(ROWB, 1), 256>>>(x, nullptr, nullptr, w_g0, b_g0, pt16);

    // #1,#2: dense fp16 a_hat (deterministic; replaces all CSR machinery)
    prep_deg<<<NN, 128>>>(adj);
    prep_fill_dense<<<NP, 256>>>(adj);

    // #3: layer-0 SpMM-as-MMA  ← ncu capture slot
    spmm_mma<<<dim3(4, GG), 256>>>(pt16, ps);
    bn_finalize<<<1, HID>>>(gamma + 0 * HID, beta + 0 * HID);

    // remaining input GEMMs
    gemm_tc<FIN, HID, false, false, false, false><<<dim3(ROWB, 1), 256>>>(x, nullptr, nullptr, w_r0, b_r0, pr);
    gemm_tc<FIN, OUTF, false, false, false, false><<<dim3(ROWB, 2), 256>>>(x, nullptr, nullptr, w_fr, b_fr, out);

    // layer 0 fused: h0 = relu(bn(s)) + r0; t1 = fp16(h0 @ w_g1 + b)
    gemm_tc<HID, HID, false, true, true, true><<<dim3(ROWB, 1), 256>>>(ps, pr, ph, w_g1, b_g1, pt16);

    // layer 1
    spmm_mma<<<dim3(4, GG), 256>>>(pt16, ps);
    bn_finalize<<<1, HID>>>(gamma + 1 * HID, beta + 1 * HID);
    gemm_tc<HID, HID, false, true, true, true><<<dim3(ROWB, 1), 256>>>(ps, ph, ph, w_g2, b_g2, pt16);

    // layer 2: h2 never materialized; out += h2 @ w_fc + b_fc
    spmm_mma<<<dim3(4, GG), 256>>>(pt16, ps);
    bn_finalize<<<1, HID>>>(gamma + 2 * HID, beta + 2 * HID);
    gemm_tc<HID, OUTF, true, true, false, false><<<dim3(ROWB, 2), 256>>>(ps, ph, nullptr, w_fc, b_fc, out);
}

// round 12
// speedup vs baseline: 1.6468x; 1.0992x over previous
#include <cuda_runtime.h>
#include <cuda_fp16.h>
#include <cstdint>

#define GG 512            // B*T graphs
#define NN 500            // nodes
#define NP 512            // padded node count (MMA K/M)
#define FIN 96
#define HID 64
#define OUTF 96
#define ROWS (GG*NN)      // 256000
#define BN_EPS 1e-5f

// ---------------- scratch (device globals; no allocation allowed) ----------------
// g_t16 has 16 rows of slack: padded-K B-reads (rows 500..511) land there.
// Device globals are zero-initialized and the slack is never written -> reads 0.
__device__ __half2 g_t16[((long)ROWS + 16)*HID/2]; // GEMM output / SpMM input (fp16)
// a_hat in fragment-major layout: word @ (((tau*16 + c)*2 + s)*128 + lane*4 + reg)
// tau = 16-row group (0..31), c = 32k-chunk (0..15), s = k16 step (0..1),
// lane = (g<<2)|t4, reg = m16n8k16 A-register index (0..3).
__device__ uint32_t g_afrag[32*16*2*128];          // 131072 words = 512KB
__device__ float g_s[(long)ROWS*HID];    // SpMM output
__device__ float g_h[(long)ROWS*HID];    // layer activations (residual chain)
__device__ float g_r[(long)ROWS*HID];    // layer-0 residual (x @ w_r0 + b_r0)
__device__ float g_dinv[NN];
__device__ float g_sum[HID];
__device__ float g_sumsq[HID];
__device__ float g_scale[HID];
__device__ float g_shift[HID];

// ---------------- prep 1: degrees -> dinv ----------------
__global__ void prep_deg(const float* __restrict__ adj) {
    int m = blockIdx.x;
    int tid = threadIdx.x;
    float sum = 0.f;
    for (int n = tid; n < NN; n += blockDim.x) sum += adj[m*NN + n];
    __shared__ float ssum[4];
    #pragma unroll
    for (int o = 16; o; o >>= 1) sum += __shfl_down_sync(0xFFFFFFFFu, sum, o);
    int w = tid >> 5;
    if ((tid & 31) == 0) ssum[w] = sum;
    __syncthreads();
    if (tid == 0)
        g_dinv[m] = rsqrtf(1.f + ssum[0] + ssum[1] + ssum[2] + ssum[3]);
    if (blockIdx.x == 0 && tid < HID) { g_sum[tid] = 0.f; g_sumsq[tid] = 0.f; }
}

// ---------------- prep 2: build fragment-major fp16 a_hat directly ----------------
__device__ __forceinline__ float ahat_val(const float* adj, const float* dinv, int m, int n) {
    if (m >= NN || n >= NN) return 0.f;
    float dm = dinv[m];
    return (n == m) ? dm * dm : adj[m*NN + n] * dm * dinv[n];
}

__global__ __launch_bounds__(256) void prep_fill_frag(const float* __restrict__ adj) {
    __shared__ float sdinv[NN];
    int tid = threadIdx.x;
    for (int i = tid; i < NN; i += 256) sdinv[i] = g_dinv[i];
    __syncthreads();
    int idx = blockIdx.x * 256 + tid;           // 0 .. 131071
    int reg = idx & 3;
    int l   = (idx >> 2) & 31;
    int s   = (idx >> 7) & 1;
    int c   = (idx >> 8) & 15;
    int tau = idx >> 12;
    int g = l >> 2, t4 = l & 3;
    int row = tau * 16 + g + (reg & 1) * 8;
    int kp  = c * 16 + s * 8 + t4 + (reg >> 1) * 4;
    __half2 v = __floats2half2_rn(ahat_val(adj, sdinv, row, 2*kp),
                                  ahat_val(adj, sdinv, row, 2*kp + 1));
    g_afrag[idx] = *(uint32_t*)&v;
}

// ---------------- fp16 MMA helpers ----------------
__device__ __forceinline__ uint32_t h2u(__half2 h) { return *(uint32_t*)&h; }

__device__ __forceinline__ void f16_split2(float a, float b, uint32_t& hi, uint32_t& lo) {
    __half2 h = __floats2half2_rn(a, b);
    float2 back = __half22float2(h);
    __half2 l = __floats2half2_rn(a - back.x, b - back.y);
    hi = h2u(h); lo = h2u(l);
}

__device__ __forceinline__ void mma_f16(float* c, const uint32_t* a, const uint32_t* b) {
    asm volatile(
        "mma.sync.aligned.m16n8k16.row.col.f32.f16.f16.f32 "
        "{%0,%1,%2,%3}, {%4,%5,%6,%7}, {%8,%9}, {%0,%1,%2,%3};\n"
        : "+f"(c[0]), "+f"(c[1]), "+f"(c[2]), "+f"(c[3])
        : "r"(a[0]), "r"(a[1]), "r"(a[2]), "r"(a[3]), "r"(b[0]), "r"(b[1]));
}

// ---------------- SpMM as batched dense MMA + fused BN stats (v2) ----------------
// grid (4, GG). A fragments come straight from g_afrag (L1-resident, no smem);
// B staged per 32-k chunk with uint4 loads + in-register half2 transpose.
__global__ __launch_bounds__(256) void spmm_mma(
    const __half2* __restrict__ T2, float* __restrict__ S)
{
    __shared__ uint32_t Bs[16][72];    // [kpair][col], stride 72 -> conflict-free frags
    __shared__ float ssum[8][32], ssq[8][32];

    const int tid = threadIdx.x;
    const int wid = tid >> 5;
    const int lane = tid & 31;
    const int g  = lane >> 2;
    const int t4 = lane & 3;
    const int warp_m = wid >> 1;
    const int warp_n = wid & 1;

    const int gph = blockIdx.y;
    const int rt = blockIdx.x;
    const __half* Tg = (const __half*)T2 + (long)gph * NN * HID;
    float* Sg = S + (long)gph * NN * HID;

    float acc[2][4][4];
    #pragma unroll
    for (int mt = 0; mt < 2; mt++)
        #pragma unroll
        for (int nt = 0; nt < 4; nt++)
            #pragma unroll
            for (int q = 0; q < 4; q++) acc[mt][nt][q] = 0.f;

    const int bkp = tid >> 3;          // 0..15 (B staging kpair, lower half only)
    const int bcq = tid & 7;           // 0..7  (8-channel group)

    for (int c = 0; c < 16; c++) {
        // --- stage B: 32 k x 64 ch via uint4 loads + half2 transpose ---
        if (tid < 128) {
            long k = c * 32 + 2 * bkp;
            uint4 lo = *(const uint4*)(Tg + k * HID + bcq * 8);
            uint4 hi = *(const uint4*)(Tg + (k + 1) * HID + bcq * 8);
            const __half2* l2 = (const __half2*)&lo;
            const __half2* h2 = (const __half2*)&hi;
            uint32_t w[8];
            #pragma unroll
            for (int j = 0; j < 4; j++) {
                w[2*j]   = h2u(__lows2half2(l2[j], h2[j]));
                w[2*j+1] = h2u(__highs2half2(l2[j], h2[j]));
            }
            *(uint4*)&Bs[bkp][bcq*8]     = make_uint4(w[0], w[1], w[2], w[3]);
            *(uint4*)&Bs[bkp][bcq*8 + 4] = make_uint4(w[4], w[5], w[6], w[7]);
        }
        __syncthreads();

        #pragma unroll
        for (int s = 0; s < 2; s++) {
            uint32_t a[2][4], b[4][2];
            #pragma unroll
            for (int mt = 0; mt < 2; mt++) {
                int tau = rt * 8 + warp_m * 2 + mt;
                const uint4 v = *(const uint4*)(g_afrag + (((tau*16 + c)*2 + s)*128 + lane*4));
                a[mt][0] = v.x; a[mt][1] = v.y; a[mt][2] = v.z; a[mt][3] = v.w;
            }
            #pragma unroll
            for (int nt = 0; nt < 4; nt++) {
                int nb = warp_n * 32 + nt * 8 + g;
                int kr = s * 8 + t4;
                b[nt][0] = Bs[kr][nb];    b[nt][1] = Bs[kr+4][nb];
            }
            #pragma unroll
            for (int mt = 0; mt < 2; mt++)
                #pragma unroll
                for (int nt = 0; nt < 4; nt++)
                    mma_f16(acc[mt][nt], a[mt], b[nt]);
        }
        __syncthreads();
    }

    // --- epilogue: store S (guard row < 500) ---
    const int row0 = rt * 128;
    #pragma unroll
    for (int mt = 0; mt < 2; mt++) {
        int rowa = row0 + warp_m * 32 + mt * 16 + g;
        int rowb = rowa + 8;
        #pragma unroll
        for (int nt = 0; nt < 4; nt++) {
            int col = warp_n * 32 + nt * 8 + 2 * t4;
            if (rowa < NN)
                *(float2*)(Sg + (long)rowa * HID + col) = make_float2(acc[mt][nt][0], acc[mt][nt][1]);
            if (rowb < NN)
                *(float2*)(Sg + (long)rowb * HID + col) = make_float2(acc[mt][nt][2], acc[mt][nt][3]);
        }
    }

    // --- BN stats: rows >= 500 are exactly zero (zero A rows), contribute nothing ---
    float ls[8], lq[8];
    #pragma unroll
    for (int nt = 0; nt < 4; nt++)
        #pragma unroll
        for (int b = 0; b < 2; b++) {
            float v0 = acc[0][nt][b], v1 = acc[0][nt][b+2];
            float v2 = acc[1][nt][b], v3 = acc[1][nt][b+2];
            ls[nt*2+b] = v0 + v1 + v2 + v3;
            lq[nt*2+b] = v0*v0 + v1*v1 + v2*v2 + v3*v3;
        }
    #pragma unroll
    for (int i = 0; i < 8; i++) {
        #pragma unroll
        for (int off = 4; off <= 16; off <<= 1) {
            ls[i] += __shfl_xor_sync(0xFFFFFFFFu, ls[i], off);
            lq[i] += __shfl_xor_sync(0xFFFFFFFFu, lq[i], off);
        }
    }
    if (lane < 4) {
        #pragma unroll
        for (int nt = 0; nt < 4; nt++)
            #pragma unroll
            for (int b = 0; b < 2; b++) {
                ssum[wid][nt*8 + 2*lane + b] = ls[nt*2+b];
                ssq [wid][nt*8 + 2*lane + b] = lq[nt*2+b];
            }
    }
    __syncthreads();
    if (tid < 128) {
        int col = tid & 63;
        int wn = col >> 5, lc = col & 31;
        bool isq = tid >= 64;
        float t = 0.f;
        #pragma unroll
        for (int w = 0; w < 4; w++) {
            int wd = w * 2 + wn;
            t += isq ? ssq[wd][lc] : ssum[wd][lc];
        }
        atomicAdd(isq ? &g_sumsq[col] : &g_sum[col], t);
    }
}

// ---------------- tensor-core GEMM: fp16 2-way split, m16n8k16, fp32 accum ------
// (validated in R10/R11 at rel_err 1.42e-4 / 1.91e-4)
template<int K, int C, bool ACCUM, bool FUSE, bool WRITE_H, bool OUT_HALF>
__global__ __launch_bounds__(256) void gemm_tc(
    const float* __restrict__ A, const float* __restrict__ R, float* __restrict__ Hout,
    const float* __restrict__ Bw, const float* __restrict__ bias, void* __restrict__ Cout)
{
    __shared__ uint32_t AsH[128][20], AsL[128][20];
    __shared__ uint32_t BsH[16][72],  BsL[16][72];
    __shared__ float s_scale[HID], s_shift[HID];

    const int tid = threadIdx.x;
    const int wid = tid >> 5;
    const int lane = tid & 31;
    const int g  = lane >> 2;
    const int t4 = lane & 3;
    const int warp_m = wid >> 1;
    const int warp_n = wid & 1;

    const long row0 = (long)blockIdx.x * 128;
    const int col0 = blockIdx.y * 64;

    if (FUSE) {
        if (tid < HID) s_scale[tid] = g_scale[tid];
        else if (tid < 2*HID) s_shift[tid - HID] = g_shift[tid - HID];
        __syncthreads();
    }

    float acc[2][4][4];
    #pragma unroll
    for (int mt = 0; mt < 2; mt++)
        #pragma unroll
        for (int nt = 0; nt < 4; nt++)
            #pragma unroll
            for (int q = 0; q < 4; q++) acc[mt][nt][q] = 0.f;

    for (int k0 = 0; k0 < K; k0 += 32) {
        #pragma unroll
        for (int i = 0; i < 4; i++) {
            int idx = tid + i * 256;
            int r = idx >> 3;
            int q = idx & 7;
            long off = (row0 + r) * K + (k0 + q * 4);
            float4 v = *(const float4*)(A + off);
            if (FUSE) {
                int kc = k0 + q * 4;
                float4 rv = *(const float4*)(R + off);
                v.x = fmaxf(v.x * s_scale[kc+0] + s_shift[kc+0], 0.f) + rv.x;
                v.y = fmaxf(v.y * s_scale[kc+1] + s_shift[kc+1], 0.f) + rv.y;
                v.z = fmaxf(v.z * s_scale[kc+2] + s_shift[kc+2], 0.f) + rv.z;
                v.w = fmaxf(v.w * s_scale[kc+3] + s_shift[kc+3], 0.f) + rv.w;
                if (WRITE_H) *(float4*)(Hout + off) = v;
            }
            uint32_t h01, l01, h23, l23;
            f16_split2(v.x, v.y, h01, l01);
            f16_split2(v.z, v.w, h23, l23);
            *(uint2*)&AsH[r][q*2] = make_uint2(h01, h23);
            *(uint2*)&AsL[r][q*2] = make_uint2(l01, l23);
        }
        {
            int kk = tid >> 4;
            int cq = tid & 15;
            int c = col0 + cq * 4;
            float4 v0 = make_float4(0.f,0.f,0.f,0.f);
            float4 v1 = make_float4(0.f,0.f,0.f,0.f);
            if ((C & 63) == 0 || c < C) {
                v0 = *(const float4*)(Bw + (k0 + 2*kk    ) * C + c);
                v1 = *(const float4*)(Bw + (k0 + 2*kk + 1) * C + c);
            }
            uint32_t h, l;
            f16_split2(v0.x, v1.x, h, l); BsH[kk][cq*4+0] = h; BsL[kk][cq*4+0] = l;
            f16_split2(v0.y, v1.y, h, l); BsH[kk][cq*4+1] = h; BsL[kk][cq*4+1] = l;
            f16_split2(v0.z, v1.z, h, l); BsH[kk][cq*4+2] = h; BsL[kk][cq*4+2] = l;
            f16_split2(v0.w, v1.w, h, l); BsH[kk][cq*4+3] = h; BsL[kk][cq*4+3] = l;
        }
        __syncthreads();

        #pragma unroll
        for (int s = 0; s < 2; s++) {
            uint32_t ah[2][4], al[2][4];
            #pragma unroll
            for (int mt = 0; mt < 2; mt++) {
                int r = warp_m * 32 + mt * 16 + g;
                int kc = s * 8 + t4;
                ah[mt][0] = AsH[r][kc];     al[mt][0] = AsL[r][kc];
                ah[mt][1] = AsH[r+8][kc];   al[mt][1] = AsL[r+8][kc];
                ah[mt][2] = AsH[r][kc+4];   al[mt][2] = AsL[r][kc+4];
                ah[mt][3] = AsH[r+8][kc+4]; al[mt][3] = AsL[r+8][kc+4];
            }
            uint32_t bh[4][2], bl[4][2];
            #pragma unroll
            for (int nt = 0; nt < 4; nt++) {
                int nb = warp_n * 32 + nt * 8 + g;
                int kr = s * 8 + t4;
                bh[nt][0] = BsH[kr][nb];    bl[nt][0] = BsL[kr][nb];
                bh[nt][1] = BsH[kr+4][nb];  bl[nt][1] = BsL[kr+4][nb];
            }
            #pragma unroll
            for (int mt = 0; mt < 2; mt++)
                #pragma unroll
                for (int nt = 0; nt < 4; nt++) {
                    mma_f16(acc[mt][nt], ah[mt], bh[nt]);
                    mma_f16(acc[mt][nt], ah[mt], bl[nt]);
                    mma_f16(acc[mt][nt], al[mt], bh[nt]);
                }
        }
        __syncthreads();
    }

    #pragma unroll
    for (int mt = 0; mt < 2; mt++) {
        long rowa = row0 + warp_m * 32 + mt * 16 + g;
        long rowb = rowa + 8;
        #pragma unroll
        for (int nt = 0; nt < 4; nt++) {
            int col = col0 + warp_n * 32 + nt * 8 + 2 * t4;
            if ((C & 63) == 0 || col < C) {
                float bx = bias[col];
                float by = bias[col + 1];
                float2 v0 = make_float2(acc[mt][nt][0] + bx, acc[mt][nt][1] + by);
                float2 v1 = make_float2(acc[mt][nt][2] + bx, acc[mt][nt][3] + by);
                if (OUT_HALF) {
                    __half2* o = (__half2*)Cout;
                    o[(rowa * C + col) >> 1] = __floats2half2_rn(v0.x, v0.y);
                    o[(rowb * C + col) >> 1] = __floats2half2_rn(v1.x, v1.y);
                } else {
                    float* d0 = (float*)Cout + rowa * C + col;
                    float* d1 = (float*)Cout + rowb * C + col;
                    if (ACCUM) {
                        float2 o0 = *(const float2*)d0;
                        float2 o1 = *(const float2*)d1;
                        v0.x += o0.x; v0.y += o0.y;
                        v1.x += o1.x; v1.y += o1.y;
                    }
                    *(float2*)d0 = v0;
                    *(float2*)d1 = v1;
                }
            }
        }
    }
}

// ---------------- fused input GEMM: t0 = fp16(x@w0+b0), r0 = x@w1+b1 ----------------
// A (x, K=96) staged + split ONCE into resident smem (stride 52 -> conflict-free),
// then two B phases. Saves a full pass of x reads + A split work.
#define IN2_SMEM_WORDS (2 * 128 * 52)
#define IN2_SMEM_BYTES (IN2_SMEM_WORDS * 4)

__global__ __launch_bounds__(256) void gemm_in2(
    const float* __restrict__ A,
    const float* __restrict__ w0, const float* __restrict__ b0, __half2* __restrict__ T,
    const float* __restrict__ w1, const float* __restrict__ b1, float* __restrict__ Rr)
{
    extern __shared__ uint32_t dsm[];
    uint32_t (*AsH)[52] = (uint32_t(*)[52])(dsm);
    uint32_t (*AsL)[52] = (uint32_t(*)[52])(dsm + 128*52);
    __shared__ uint32_t BsH[16][72], BsL[16][72];

    const int tid = threadIdx.x;
    const int wid = tid >> 5;
    const int lane = tid & 31;
    const int g  = lane >> 2;
    const int t4 = lane & 3;
    const int warp_m = wid >> 1;
    const int warp_n = wid & 1;
    const long row0 = (long)blockIdx.x * 128;

    // stage + split full A tile: 128 rows x 96 k  (3072 float4 tasks, 12/thread)
    #pragma unroll
    for (int i = 0; i < 12; i++) {
        int idx = tid + i * 256;
        int r = idx / 24;
        int q = idx % 24;                  // float4 index: k = 4q..4q+3
        float4 v = *(const float4*)(A + (row0 + r) * FIN + q * 4);
        uint32_t h01, l01, h23, l23;
        f16_split2(v.x, v.y, h01, l01);
        f16_split2(v.z, v.w, h23, l23);
        *(uint2*)&AsH[r][q*2] = make_uint2(h01, h23);
        *(uint2*)&AsL[r][q*2] = make_uint2(l01, l23);
    }

    #pragma unroll
    for (int phase = 0; phase < 2; phase++) {
        const float* Bw  = phase ? w1 : w0;
        const float* bia = phase ? b1 : b0;
        float acc[2][4][4];
        #pragma unroll
        for (int mt = 0; mt < 2; mt++)
            #pragma unroll
            for (int nt = 0; nt < 4; nt++)
                #pragma unroll
                for (int q = 0; q < 4; q++) acc[mt][nt][q] = 0.f;

        for (int chunk = 0; chunk < 3; chunk++) {
            int k0 = chunk * 32;
            __syncthreads();               // protect Bs (and A on first pass)
            {
                int kk = tid >> 4;
                int cq = tid & 15;
                int c = cq * 4;
                float4 v0 = *(const float4*)(Bw + (k0 + 2*kk    ) * HID + c);
                float4 v1 = *(const float4*)(Bw + (k0 + 2*kk + 1) * HID + c);
                uint32_t h, l;
                f16_split2(v0.x, v1.x, h, l); BsH[kk][cq*4+0] = h; BsL[kk][cq*4+0] = l;
                f16_split2(v0.y, v1.y, h, l); BsH[kk][cq*4+1] = h; BsL[kk][cq*4+1] = l;
                f16_split2(v0.z, v1.z, h, l); BsH[kk][cq*4+2] = h; BsL[kk][cq*4+2] = l;
                f16_split2(v0.w, v1.w, h, l); BsH[kk][cq*4+3] = h; BsL[kk][cq*4+3] = l;
            }
            __syncthreads();

            #pragma unroll
            for (int s = 0; s < 2; s++) {
                uint32_t ah[2][4], al[2][4];
                #pragma unroll
                for (int mt = 0; mt < 2; mt++) {
                    int r = warp_m * 32 + mt * 16 + g;
                    int kc = chunk * 16 + s * 8 + t4;
                    ah[mt][0] = AsH[r][kc];     al[mt][0] = AsL[r][kc];
                    ah[mt][1] = AsH[r+8][kc];   al[mt][1] = AsL[r+8][kc];
                    ah[mt][2] = AsH[r][kc+4];   al[mt][2] = AsL[r][kc+4];
                    ah[mt][3] = AsH[r+8][kc+4]; al[mt][3] = AsL[r+8][kc+4];
                }
                uint32_t bh[4][2], bl[4][2];
                #pragma unroll
                for (int nt = 0; nt < 4; nt++) {
                    int nb = warp_n * 32 + nt * 8 + g;
                    int kr = s * 8 + t4;
                    bh[nt][0] = BsH[kr][nb];    bl[nt][0] = BsL[kr][nb];
                    bh[nt][1] = BsH[kr+4][nb];  bl[nt][1] = BsL[kr+4][nb];
                }
                #pragma unroll
                for (int mt = 0; mt < 2; mt++)
                    #pragma unroll
                    for (int nt = 0; nt < 4; nt++) {
                        mma_f16(acc[mt][nt], ah[mt], bh[nt]);
                        mma_f16(acc[mt][nt], ah[mt], bl[nt]);
                        mma_f16(acc[mt][nt], al[mt], bh[nt]);
                    }
            }
        }

        #pragma unroll
        for (int mt = 0; mt < 2; mt++) {
            long rowa = row0 + warp_m * 32 + mt * 16 + g;
            long rowb = rowa + 8;
            #pragma unroll
            for (int nt = 0; nt < 4; nt++) {
                int col = warp_n * 32 + nt * 8 + 2 * t4;
                float bx = bia[col];
                float by = bia[col + 1];
                float2 v0 = make_float2(acc[mt][nt][0] + bx, acc[mt][nt][1] + by);
                float2 v1 = make_float2(acc[mt][nt][2] + bx, acc[mt][nt][3] + by);
                if (phase == 0) {
                    T[(rowa * HID + col) >> 1] = __floats2half2_rn(v0.x, v0.y);
                    T[(rowb * HID + col) >> 1] = __floats2half2_rn(v1.x, v1.y);
                } else {
                    *(float2*)(Rr + rowa * HID + col) = v0;
                    *(float2*)(Rr + rowb * HID + col) = v1;
                }
            }
        }
    }
}

// ---------------- BN finalize ----------------
__global__ void bn_finalize(const float* __restrict__ gamma, const float* __restrict__ beta) {
    int c = threadIdx.x;
    float s = g_sum[c], q = g_sumsq[c];
    const float inv = 1.f / (float)ROWS;
    float mean = s * inv;
    float var = q * inv - mean * mean;
    float rstd = rsqrtf(var + BN_EPS);
    float a = rstd * gamma[c];
    g_scale[c] = a;
    g_shift[c] = beta[c] - mean * a;
    g_sum[c] = 0.f; g_sumsq[c] = 0.f;
}

// ---------------- launch ----------------
extern "C" void kernel_launch(void* const* d_in, const int* in_sizes, int n_in,
                              void* d_out, int out_size)
{
    const float* x     = (const float*)d_in[0];
    const float* adj   = (const float*)d_in[1];
    const float* w_g0  = (const float*)d_in[2];
    const float* b_g0  = (const float*)d_in[3];
    const float* w_g1  = (const float*)d_in[4];
    const float* b_g1  = (const float*)d_in[5];
    const float* w_g2  = (const float*)d_in[6];
    const float* b_g2  = (const float*)d_in[7];
    const float* gamma = (const float*)d_in[8];
    const float* beta  = (const float*)d_in[9];
    const float* w_r0  = (const float*)d_in[10];
    const float* b_r0  = (const float*)d_in[11];
    const float* w_fc  = (const float*)d_in[12];
    const float* b_fc  = (const float*)d_in[13];
    const float* w_fr  = (const float*)d_in[14];
    const float* b_fr  = (const float*)d_in[15];
    float* out = (float*)d_out;

    __half2 *pt16;
    float *ps, *ph, *pr;
    cudaGetSymbolAddress((void**)&pt16, g_t16);
    cudaGetSymbolAddress((void**)&ps, g_s);
    cudaGetSymbolAddress((void**)&ph, g_h);
    cudaGetSymbolAddress((void**)&pr, g_r);

    const int ROWB = ROWS / 128;               // 2000

    cudaFuncSetAttribute(gemm_in2,
                         cudaFuncAttributeMaxDynamicSharedMemorySize, IN2_SMEM_BYTES);

    // #0: t0 = fp16(x@w_g0+b0) AND r0 = x@w_r0+b_r0 (fused, x read once)
    gemm_in2<<<ROWB, 256, IN2_SMEM_BYTES>>>(x, w_g0, b_g0, pt16, w_r0, b_r0, pr);

    // #1,#2: fragment-major fp16 a_hat (deterministic)
    prep_deg<<<NN, 128>>>(adj);
    prep_fill_frag<<<512, 256>>>(adj);

    // #3: layer-0 SpMM-as-MMA  ← ncu capture slot
    spmm_mma<<<dim3(4, GG), 256>>>(pt16, ps);
    bn_finalize<<<1, HID>>>(gamma + 0 * HID, beta + 0 * HID);

    // out = x@w_fr + b_fr
    gemm_tc<FIN, OUTF, false, false, false, false><<<dim3(ROWB, 2), 256>>>(x, nullptr, nullptr, w_fr, b_fr, out);

    // layer 0 fused: h0 = relu(bn(s)) + r0; t1 = fp16(h0 @ w_g1 + b)
    gemm_tc<HID, HID, false, true, true, true><<<dim3(ROWB, 1), 256>>>(ps, pr, ph, w_g1, b_g1, pt16);

    // layer 1
    spmm_mma<<<dim3(4, GG), 256>>>(pt16, ps);
    bn_finalize<<<1, HID>>>(gamma + 1 * HID, beta + 1 * HID);
    gemm_tc<HID, HID, false, true, true, true><<<dim3(ROWB, 1), 256>>>(ps, ph, ph, w_g2, b_g2, pt16);

    // layer 2: h2 never materialized; out += h2 @ w_fc + b_fc
    spmm_mma<<<dim3(4, GG), 256>>>(pt16, ps);
    bn_finalize<<<1, HID>>>(gamma + 2 * HID, beta + 2 * HID);
    gemm_tc<HID, OUTF, true, true, false, false><<<dim3(ROWB, 2), 256>>>(ps, ph, nullptr, w_fc, b_fc, out);
}

// round 13
// speedup vs baseline: 1.7509x; 1.0632x over previous
#include <cuda_runtime.h>
#include <cuda_fp16.h>
#include <cstdint>

#define GG 512            // B*T graphs
#define NN 500            // nodes
#define NP 512            // padded node count (MMA K/M)
#define FIN 96
#define HID 64
#define OUTF 96
#define ROWS (GG*NN)      // 256000
#define BN_EPS 1e-5f

// ---------------- scratch (device globals; no allocation allowed) ----------------
// g_t16 has 16 rows of slack: padded-K B-reads (rows 500..511) land there.
// Device globals are zero-initialized and the slack is never written -> reads 0.
__device__ __half2 g_t16[((long)ROWS + 16)*HID/2]; // GEMM output / SpMM input (fp16)
// a_hat in fragment-major layout: word @ (((tau*16 + c)*2 + s)*128 + lane*4 + reg)
__device__ uint32_t g_afrag[32*16*2*128];          // 131072 words = 512KB
__device__ float g_s[(long)ROWS*HID];    // SpMM output
__device__ float g_h[(long)ROWS*HID];    // layer activations (residual chain)
__device__ float g_r[(long)ROWS*HID];    // layer-0 residual (x @ w_r0 + b_r0)
__device__ float g_dinv[NN];
__device__ float g_sum[HID];
__device__ float g_sumsq[HID];
__device__ float g_scale[HID];
__device__ float g_shift[HID];

// ---------------- prep 1: degrees -> dinv ----------------
__global__ void prep_deg(const float* __restrict__ adj) {
    int m = blockIdx.x;
    int tid = threadIdx.x;
    float sum = 0.f;
    for (int n = tid; n < NN; n += blockDim.x) sum += adj[m*NN + n];
    __shared__ float ssum[4];
    #pragma unroll
    for (int o = 16; o; o >>= 1) sum += __shfl_down_sync(0xFFFFFFFFu, sum, o);
    int w = tid >> 5;
    if ((tid & 31) == 0) ssum[w] = sum;
    __syncthreads();
    if (tid == 0)
        g_dinv[m] = rsqrtf(1.f + ssum[0] + ssum[1] + ssum[2] + ssum[3]);
    if (blockIdx.x == 0 && tid < HID) { g_sum[tid] = 0.f; g_sumsq[tid] = 0.f; }
}

// ---------------- prep 2: build fragment-major fp16 a_hat directly ----------------
__device__ __forceinline__ float ahat_val(const float* adj, const float* dinv, int m, int n) {
    if (m >= NN || n >= NN) return 0.f;
    float dm = dinv[m];
    return (n == m) ? dm * dm : adj[m*NN + n] * dm * dinv[n];
}

__global__ __launch_bounds__(256) void prep_fill_frag(const float* __restrict__ adj) {
    __shared__ float sdinv[NN];
    int tid = threadIdx.x;
    for (int i = tid; i < NN; i += 256) sdinv[i] = g_dinv[i];
    __syncthreads();
    int idx = blockIdx.x * 256 + tid;           // 0 .. 131071
    int reg = idx & 3;
    int l   = (idx >> 2) & 31;
    int s   = (idx >> 7) & 1;
    int c   = (idx >> 8) & 15;
    int tau = idx >> 12;
    int g = l >> 2, t4 = l & 3;
    int row = tau * 16 + g + (reg & 1) * 8;
    int kp  = c * 16 + s * 8 + t4 + (reg >> 1) * 4;
    __half2 v = __floats2half2_rn(ahat_val(adj, sdinv, row, 2*kp),
                                  ahat_val(adj, sdinv, row, 2*kp + 1));
    g_afrag[idx] = *(uint32_t*)&v;
}

// ---------------- fp16 MMA helpers ----------------
__device__ __forceinline__ uint32_t h2u(__half2 h) { return *(uint32_t*)&h; }

__device__ __forceinline__ void f16_split2(float a, float b, uint32_t& hi, uint32_t& lo) {
    __half2 h = __floats2half2_rn(a, b);
    float2 back = __half22float2(h);
    __half2 l = __floats2half2_rn(a - back.x, b - back.y);
    hi = h2u(h); lo = h2u(l);
}

__device__ __forceinline__ void mma_f16(float* c, const uint32_t* a, const uint32_t* b) {
    asm volatile(
        "mma.sync.aligned.m16n8k16.row.col.f32.f16.f16.f32 "
        "{%0,%1,%2,%3}, {%4,%5,%6,%7}, {%8,%9}, {%0,%1,%2,%3};\n"
        : "+f"(c[0]), "+f"(c[1]), "+f"(c[2]), "+f"(c[3])
        : "r"(a[0]), "r"(a[1]), "r"(a[2]), "r"(a[3]), "r"(b[0]), "r"(b[1]));
}

// ---------------- SpMM as batched dense MMA + fused BN stats (v3) ----------------
// grid (4, GG). A fragments straight from g_afrag (L1-resident, no smem).
// B staging DOUBLE-BUFFERED: prefetch chunk c+1 during chunk c MMAs; one sync
// per chunk (16 total vs 32), stage latency overlapped with tensor issue.
__global__ __launch_bounds__(256) void spmm_mma(
    const __half2* __restrict__ T2, float* __restrict__ S)
{
    __shared__ uint32_t Bs[2][16][72];
    __shared__ float ssum[8][32], ssq[8][32];

    const int tid = threadIdx.x;
    const int wid = tid >> 5;
    const int lane = tid & 31;
    const int g  = lane >> 2;
    const int t4 = lane & 3;
    const int warp_m = wid >> 1;
    const int warp_n = wid & 1;

    const int gph = blockIdx.y;
    const int rt = blockIdx.x;
    const __half* Tg = (const __half*)T2 + (long)gph * NN * HID;
    float* Sg = S + (long)gph * NN * HID;

    const int bkp = tid >> 3;          // 0..15 (staging kpair; lower 128 threads)
    const int bcq = tid & 7;           // 0..7  (8-channel group)

    auto stageB = [&](int c, uint32_t (*B)[72]) {
        long k = c * 32 + 2 * bkp;
        uint4 lo = *(const uint4*)(Tg + k * HID + bcq * 8);
        uint4 hi = *(const uint4*)(Tg + (k + 1) * HID + bcq * 8);
        const __half2* l2 = (const __half2*)&lo;
        const __half2* h2 = (const __half2*)&hi;
        uint32_t w[8];
        #pragma unroll
        for (int j = 0; j < 4; j++) {
            w[2*j]   = h2u(__lows2half2(l2[j], h2[j]));
            w[2*j+1] = h2u(__highs2half2(l2[j], h2[j]));
        }
        *(uint4*)&B[bkp][bcq*8]     = make_uint4(w[0], w[1], w[2], w[3]);
        *(uint4*)&B[bkp][bcq*8 + 4] = make_uint4(w[4], w[5], w[6], w[7]);
    };

    float acc[2][4][4];
    #pragma unroll
    for (int mt = 0; mt < 2; mt++)
        #pragma unroll
        for (int nt = 0; nt < 4; nt++)
            #pragma unroll
            for (int q = 0; q < 4; q++) acc[mt][nt][q] = 0.f;

    if (tid < 128) stageB(0, Bs[0]);
    __syncthreads();

    for (int c = 0; c < 16; c++) {
        int cur = c & 1;
        if (c < 15 && tid < 128) stageB(c + 1, Bs[cur ^ 1]);

        #pragma unroll
        for (int s = 0; s < 2; s++) {
            uint32_t a[2][4], b[4][2];
            #pragma unroll
            for (int mt = 0; mt < 2; mt++) {
                int tau = rt * 8 + warp_m * 2 + mt;
                const uint4 v = *(const uint4*)(g_afrag + (((tau*16 + c)*2 + s)*128 + lane*4));
                a[mt][0] = v.x; a[mt][1] = v.y; a[mt][2] = v.z; a[mt][3] = v.w;
            }
            #pragma unroll
            for (int nt = 0; nt < 4; nt++) {
                int nb = warp_n * 32 + nt * 8 + g;
                int kr = s * 8 + t4;
                b[nt][0] = Bs[cur][kr][nb];    b[nt][1] = Bs[cur][kr+4][nb];
            }
            #pragma unroll
            for (int mt = 0; mt < 2; mt++)
                #pragma unroll
                for (int nt = 0; nt < 4; nt++)
                    mma_f16(acc[mt][nt], a[mt], b[nt]);
        }
        __syncthreads();
    }

    // --- epilogue: store S (guard row < 500) ---
    const int row0 = rt * 128;
    #pragma unroll
    for (int mt = 0; mt < 2; mt++) {
        int rowa = row0 + warp_m * 32 + mt * 16 + g;
        int rowb = rowa + 8;
        #pragma unroll
        for (int nt = 0; nt < 4; nt++) {
            int col = warp_n * 32 + nt * 8 + 2 * t4;
            if (rowa < NN)
                *(float2*)(Sg + (long)rowa * HID + col) = make_float2(acc[mt][nt][0], acc[mt][nt][1]);
            if (rowb < NN)
                *(float2*)(Sg + (long)rowb * HID + col) = make_float2(acc[mt][nt][2], acc[mt][nt][3]);
        }
    }

    // --- BN stats: rows >= 500 are exactly zero (zero A rows) ---
    float ls[8], lq[8];
    #pragma unroll
    for (int nt = 0; nt < 4; nt++)
        #pragma unroll
        for (int b = 0; b < 2; b++) {
            float v0 = acc[0][nt][b], v1 = acc[0][nt][b+2];
            float v2 = acc[1][nt][b], v3 = acc[1][nt][b+2];
            ls[nt*2+b] = v0 + v1 + v2 + v3;
            lq[nt*2+b] = v0*v0 + v1*v1 + v2*v2 + v3*v3;
        }
    #pragma unroll
    for (int i = 0; i < 8; i++) {
        #pragma unroll
        for (int off = 4; off <= 16; off <<= 1) {
            ls[i] += __shfl_xor_sync(0xFFFFFFFFu, ls[i], off);
            lq[i] += __shfl_xor_sync(0xFFFFFFFFu, lq[i], off);
        }
    }
    if (lane < 4) {
        #pragma unroll
        for (int nt = 0; nt < 4; nt++)
            #pragma unroll
            for (int b = 0; b < 2; b++) {
                ssum[wid][nt*8 + 2*lane + b] = ls[nt*2+b];
                ssq [wid][nt*8 + 2*lane + b] = lq[nt*2+b];
            }
    }
    __syncthreads();
    if (tid < 128) {
        int col = tid & 63;
        int wn = col >> 5, lc = col & 31;
        bool isq = tid >= 64;
        float t = 0.f;
        #pragma unroll
        for (int w = 0; w < 4; w++) {
            int wd = w * 2 + wn;
            t += isq ? ssq[wd][lc] : ssum[wd][lc];
        }
        atomicAdd(isq ? &g_sumsq[col] : &g_sum[col], t);
    }
}

// ---------------- tensor-core GEMM: fp16 2-way split, m16n8k16, fp32 accum ------
// (validated in R10-R12; used for the fused layer GEMMs + final)
template<int K, int C, bool ACCUM, bool FUSE, bool WRITE_H, bool OUT_HALF>
__global__ __launch_bounds__(256) void gemm_tc(
    const float* __restrict__ A, const float* __restrict__ R, float* __restrict__ Hout,
    const float* __restrict__ Bw, const float* __restrict__ bias, void* __restrict__ Cout)
{
    __shared__ uint32_t AsH[128][20], AsL[128][20];
    __shared__ uint32_t BsH[16][72],  BsL[16][72];
    __shared__ float s_scale[HID], s_shift[HID];

    const int tid = threadIdx.x;
    const int wid = tid >> 5;
    const int lane = tid & 31;
    const int g  = lane >> 2;
    const int t4 = lane & 3;
    const int warp_m = wid >> 1;
    const int warp_n = wid & 1;

    const long row0 = (long)blockIdx.x * 128;
    const int col0 = blockIdx.y * 64;

    if (FUSE) {
        if (tid < HID) s_scale[tid] = g_scale[tid];
        else if (tid < 2*HID) s_shift[tid - HID] = g_shift[tid - HID];
        __syncthreads();
    }

    float acc[2][4][4];
    #pragma unroll
    for (int mt = 0; mt < 2; mt++)
        #pragma unroll
        for (int nt = 0; nt < 4; nt++)
            #pragma unroll
            for (int q = 0; q < 4; q++) acc[mt][nt][q] = 0.f;

    for (int k0 = 0; k0 < K; k0 += 32) {
        #pragma unroll
        for (int i = 0; i < 4; i++) {
            int idx = tid + i * 256;
            int r = idx >> 3;
            int q = idx & 7;
            long off = (row0 + r) * K + (k0 + q * 4);
            float4 v = *(const float4*)(A + off);
            if (FUSE) {
                int kc = k0 + q * 4;
                float4 rv = *(const float4*)(R + off);
                v.x = fmaxf(v.x * s_scale[kc+0] + s_shift[kc+0], 0.f) + rv.x;
                v.y = fmaxf(v.y * s_scale[kc+1] + s_shift[kc+1], 0.f) + rv.y;
                v.z = fmaxf(v.z * s_scale[kc+2] + s_shift[kc+2], 0.f) + rv.z;
                v.w = fmaxf(v.w * s_scale[kc+3] + s_shift[kc+3], 0.f) + rv.w;
                if (WRITE_H) *(float4*)(Hout + off) = v;
            }
            uint32_t h01, l01, h23, l23;
            f16_split2(v.x, v.y, h01, l01);
            f16_split2(v.z, v.w, h23, l23);
            *(uint2*)&AsH[r][q*2] = make_uint2(h01, h23);
            *(uint2*)&AsL[r][q*2] = make_uint2(l01, l23);
        }
        {
            int kk = tid >> 4;
            int cq = tid & 15;
            int c = col0 + cq * 4;
            float4 v0 = make_float4(0.f,0.f,0.f,0.f);
            float4 v1 = make_float4(0.f,0.f,0.f,0.f);
            if ((C & 63) == 0 || c < C) {
                v0 = *(const float4*)(Bw + (k0 + 2*kk    ) * C + c);
                v1 = *(const float4*)(Bw + (k0 + 2*kk + 1) * C + c);
            }
            uint32_t h, l;
            f16_split2(v0.x, v1.x, h, l); BsH[kk][cq*4+0] = h; BsL[kk][cq*4+0] = l;
            f16_split2(v0.y, v1.y, h, l); BsH[kk][cq*4+1] = h; BsL[kk][cq*4+1] = l;
            f16_split2(v0.z, v1.z, h, l); BsH[kk][cq*4+2] = h; BsL[kk][cq*4+2] = l;
            f16_split2(v0.w, v1.w, h, l); BsH[kk][cq*4+3] = h; BsL[kk][cq*4+3] = l;
        }
        __syncthreads();

        #pragma unroll
        for (int s = 0; s < 2; s++) {
            uint32_t ah[2][4], al[2][4];
            #pragma unroll
            for (int mt = 0; mt < 2; mt++) {
                int r = warp_m * 32 + mt * 16 + g;
                int kc = s * 8 + t4;
                ah[mt][0] = AsH[r][kc];     al[mt][0] = AsL[r][kc];
                ah[mt][1] = AsH[r+8][kc];   al[mt][1] = AsL[r+8][kc];
                ah[mt][2] = AsH[r][kc+4];   al[mt][2] = AsL[r][kc+4];
                ah[mt][3] = AsH[r+8][kc+4]; al[mt][3] = AsL[r+8][kc+4];
            }
            uint32_t bh[4][2], bl[4][2];
            #pragma unroll
            for (int nt = 0; nt < 4; nt++) {
                int nb = warp_n * 32 + nt * 8 + g;
                int kr = s * 8 + t4;
                bh[nt][0] = BsH[kr][nb];    bl[nt][0] = BsL[kr][nb];
                bh[nt][1] = BsH[kr+4][nb];  bl[nt][1] = BsL[kr+4][nb];
            }
            #pragma unroll
            for (int mt = 0; mt < 2; mt++)
                #pragma unroll
                for (int nt = 0; nt < 4; nt++) {
                    mma_f16(acc[mt][nt], ah[mt], bh[nt]);
                    mma_f16(acc[mt][nt], ah[mt], bl[nt]);
                    mma_f16(acc[mt][nt], al[mt], bh[nt]);
                }
        }
        __syncthreads();
    }

    #pragma unroll
    for (int mt = 0; mt < 2; mt++) {
        long rowa = row0 + warp_m * 32 + mt * 16 + g;
        long rowb = rowa + 8;
        #pragma unroll
        for (int nt = 0; nt < 4; nt++) {
            int col = col0 + warp_n * 32 + nt * 8 + 2 * t4;
            if ((C & 63) == 0 || col < C) {
                float bx = bias[col];
                float by = bias[col + 1];
                float2 v0 = make_float2(acc[mt][nt][0] + bx, acc[mt][nt][1] + by);
                float2 v1 = make_float2(acc[mt][nt][2] + bx, acc[mt][nt][3] + by);
                if (OUT_HALF) {
                    __half2* o = (__half2*)Cout;
                    o[(rowa * C + col) >> 1] = __floats2half2_rn(v0.x, v0.y);
                    o[(rowb * C + col) >> 1] = __floats2half2_rn(v1.x, v1.y);
                } else {
                    float* d0 = (float*)Cout + rowa * C + col;
                    float* d1 = (float*)Cout + rowb * C + col;
                    if (ACCUM) {
                        float2 o0 = *(const float2*)d0;
                        float2 o1 = *(const float2*)d1;
                        v0.x += o0.x; v0.y += o0.y;
                        v1.x += o1.x; v1.y += o1.y;
                    }
                    *(float2*)d0 = v0;
                    *(float2*)d1 = v1;
                }
            }
        }
    }
}

// ---------------- fused input GEMM (x read ONCE): t0, r0, AND out=x@w_fr+b_fr ----
// A (x, K=96) staged + split once into resident smem; 4 B phases:
//   p0: w_g0 -> T (fp16, C=64)   p1: w_r0 -> Rr (fp32, C=64)
//   p2: w_fr cols 0-63 -> Out    p3: w_fr cols 64-95 -> Out (C=96, guarded)
#define IN3_SMEM_WORDS (2 * 128 * 52)
#define IN3_SMEM_BYTES (IN3_SMEM_WORDS * 4)

__global__ __launch_bounds__(256) void gemm_in3(
    const float* __restrict__ A,
    const float* __restrict__ w_g0, const float* __restrict__ b_g0, __half2* __restrict__ T,
    const float* __restrict__ w_r0, const float* __restrict__ b_r0, float* __restrict__ Rr,
    const float* __restrict__ w_fr, const float* __restrict__ b_fr, float* __restrict__ Out)
{
    extern __shared__ uint32_t dsm[];
    uint32_t (*AsH)[52] = (uint32_t(*)[52])(dsm);
    uint32_t (*AsL)[52] = (uint32_t(*)[52])(dsm + 128*52);
    __shared__ uint32_t BsH[16][72], BsL[16][72];

    const int tid = threadIdx.x;
    const int wid = tid >> 5;
    const int lane = tid & 31;
    const int g  = lane >> 2;
    const int t4 = lane & 3;
    const int warp_m = wid >> 1;
    const int warp_n = wid & 1;
    const long row0 = (long)blockIdx.x * 128;

    // stage + split full A tile: 128 rows x 96 k  (3072 float4 tasks, 12/thread)
    #pragma unroll
    for (int i = 0; i < 12; i++) {
        int idx = tid + i * 256;
        int r = idx / 24;
        int q = idx % 24;
        float4 v = *(const float4*)(A + (row0 + r) * FIN + q * 4);
        uint32_t h01, l01, h23, l23;
        f16_split2(v.x, v.y, h01, l01);
        f16_split2(v.z, v.w, h23, l23);
        *(uint2*)&AsH[r][q*2] = make_uint2(h01, h23);
        *(uint2*)&AsL[r][q*2] = make_uint2(l01, l23);
    }

    const float* Bws[4]   = {w_g0, w_r0, w_fr, w_fr};
    const float* biass[4] = {b_g0, b_r0, b_fr, b_fr};

    #pragma unroll 1
    for (int phase = 0; phase < 4; phase++) {
        const float* Bw  = Bws[phase];
        const float* bia = biass[phase];
        const int col0 = (phase == 3) ? 64 : 0;
        const int C = (phase >= 2) ? OUTF : HID;

        float acc[2][4][4];
        #pragma unroll
        for (int mt = 0; mt < 2; mt++)
            #pragma unroll
            for (int nt = 0; nt < 4; nt++)
                #pragma unroll
                for (int q = 0; q < 4; q++) acc[mt][nt][q] = 0.f;

        for (int chunk = 0; chunk < 3; chunk++) {
            int k0 = chunk * 32;
            __syncthreads();               // protect Bs (and A on first pass)
            {
                int kk = tid >> 4;
                int cq = tid & 15;
                int c = col0 + cq * 4;
                float4 v0 = make_float4(0.f,0.f,0.f,0.f);
                float4 v1 = make_float4(0.f,0.f,0.f,0.f);
                if (c < C) {
                    v0 = *(const float4*)(Bw + (k0 + 2*kk    ) * C + c);
                    v1 = *(const float4*)(Bw + (k0 + 2*kk + 1) * C + c);
                }
                uint32_t h, l;
                f16_split2(v0.x, v1.x, h, l); BsH[kk][cq*4+0] = h; BsL[kk][cq*4+0] = l;
                f16_split2(v0.y, v1.y, h, l); BsH[kk][cq*4+1] = h; BsL[kk][cq*4+1] = l;
                f16_split2(v0.z, v1.z, h, l); BsH[kk][cq*4+2] = h; BsL[kk][cq*4+2] = l;
                f16_split2(v0.w, v1.w, h, l); BsH[kk][cq*4+3] = h; BsL[kk][cq*4+3] = l;
            }
            __syncthreads();

            #pragma unroll
            for (int s = 0; s < 2; s++) {
                uint32_t ah[2][4], al[2][4];
                #pragma unroll
                for (int mt = 0; mt < 2; mt++) {
                    int r = warp_m * 32 + mt * 16 + g;
                    int kc = chunk * 16 + s * 8 + t4;
                    ah[mt][0] = AsH[r][kc];     al[mt][0] = AsL[r][kc];
                    ah[mt][1] = AsH[r+8][kc];   al[mt][1] = AsL[r+8][kc];
                    ah[mt][2] = AsH[r][kc+4];   al[mt][2] = AsL[r][kc+4];
                    ah[mt][3] = AsH[r+8][kc+4]; al[mt][3] = AsL[r+8][kc+4];
                }
                uint32_t bh[4][2], bl[4][2];
                #pragma unroll
                for (int nt = 0; nt < 4; nt++) {
                    int nb = warp_n * 32 + nt * 8 + g;
                    int kr = s * 8 + t4;
                    bh[nt][0] = BsH[kr][nb];    bl[nt][0] = BsL[kr][nb];
                    bh[nt][1] = BsH[kr+4][nb];  bl[nt][1] = BsL[kr+4][nb];
                }
                #pragma unroll
                for (int mt = 0; mt < 2; mt++)
                    #pragma unroll
                    for (int nt = 0; nt < 4; nt++) {
                        mma_f16(acc[mt][nt], ah[mt], bh[nt]);
                        mma_f16(acc[mt][nt], ah[mt], bl[nt]);
                        mma_f16(acc[mt][nt], al[mt], bh[nt]);
                    }
            }
        }

        #pragma unroll
        for (int mt = 0; mt < 2; mt++) {
            long rowa = row0 + warp_m * 32 + mt * 16 + g;
            long rowb = rowa + 8;
            #pragma unroll
            for (int nt = 0; nt < 4; nt++) {
                int col = col0 + warp_n * 32 + nt * 8 + 2 * t4;
                if (col < C) {
                    float bx = bia[col];
                    float by = bia[col + 1];
                    float2 v0 = make_float2(acc[mt][nt][0] + bx, acc[mt][nt][1] + by);
                    float2 v1 = make_float2(acc[mt][nt][2] + bx, acc[mt][nt][3] + by);
                    if (phase == 0) {
                        T[(rowa * HID + col) >> 1] = __floats2half2_rn(v0.x, v0.y);
                        T[(rowb * HID + col) >> 1] = __floats2half2_rn(v1.x, v1.y);
                    } else if (phase == 1) {
                        *(float2*)(Rr + rowa * HID + col) = v0;
                        *(float2*)(Rr + rowb * HID + col) = v1;
                    } else {
                        *(float2*)(Out + rowa * OUTF + col) = v0;
                        *(float2*)(Out + rowb * OUTF + col) = v1;
                    }
                }
            }
        }
    }
}

// ---------------- BN finalize ----------------
__global__ void bn_finalize(const float* __restrict__ gamma, const float* __restrict__ beta) {
    int c = threadIdx.x;
    float s = g_sum[c], q = g_sumsq[c];
    const float inv = 1.f / (float)ROWS;
    float mean = s * inv;
    float var = q * inv - mean * mean;
    float rstd = rsqrtf(var + BN_EPS);
    float a = rstd * gamma[c];
    g_scale[c] = a;
    g_shift[c] = beta[c] - mean * a;
    g_sum[c] = 0.f; g_sumsq[c] = 0.f;
}

// ---------------- launch ----------------
extern "C" void kernel_launch(void* const* d_in, const int* in_sizes, int n_in,
                              void* d_out, int out_size)
{
    const float* x     = (const float*)d_in[0];
    const float* adj   = (const float*)d_in[1];
    const float* w_g0  = (const float*)d_in[2];
    const float* b_g0  = (const float*)d_in[3];
    const float* w_g1  = (const float*)d_in[4];
    const float* b_g1  = (const float*)d_in[5];
    const float* w_g2  = (const float*)d_in[6];
    const float* b_g2  = (const float*)d_in[7];
    const float* gamma = (const float*)d_in[8];
    const float* beta  = (const float*)d_in[9];
    const float* w_r0  = (const float*)d_in[10];
    const float* b_r0  = (const float*)d_in[11];
    const float* w_fc  = (const float*)d_in[12];
    const float* b_fc  = (const float*)d_in[13];
    const float* w_fr  = (const float*)d_in[14];
    const float* b_fr  = (const float*)d_in[15];
    float* out = (float*)d_out;

    __half2 *pt16;
    float *ps, *ph, *pr;
    cudaGetSymbolAddress((void**)&pt16, g_t16);
    cudaGetSymbolAddress((void**)&ps, g_s);
    cudaGetSymbolAddress((void**)&ph, g_h);
    cudaGetSymbolAddress((void**)&pr, g_r);

    const int ROWB = ROWS / 128;               // 2000

    cudaFuncSetAttribute(gemm_in3,
                         cudaFuncAttributeMaxDynamicSharedMemorySize, IN3_SMEM_BYTES);

    // #0: t0 = fp16(x@w_g0+b0), r0 = x@w_r0+b_r0, out = x@w_fr+b_fr (x read once)
    gemm_in3<<<ROWB, 256, IN3_SMEM_BYTES>>>(x, w_g0, b_g0, pt16,
                                            w_r0, b_r0, pr,
                                            w_fr, b_fr, out);

    // #1,#2: fragment-major fp16 a_hat (deterministic)
    prep_deg<<<NN, 128>>>(adj);
    prep_fill_frag<<<512, 256>>>(adj);

    // #3: layer-0 SpMM-as-MMA  ← ncu capture slot
    spmm_mma<<<dim3(4, GG), 256>>>(pt16, ps);
    bn_finalize<<<1, HID>>>(gamma + 0 * HID, beta + 0 * HID);

    // layer 0 fused: h0 = relu(bn(s)) + r0; t1 = fp16(h0 @ w_g1 + b)
    gemm_tc<HID, HID, false, true, true, true><<<dim3(ROWB, 1), 256>>>(ps, pr, ph, w_g1, b_g1, pt16);

    // layer 1
    spmm_mma<<<dim3(4, GG), 256>>>(pt16, ps);
    bn_finalize<<<1, HID>>>(gamma + 1 * HID, beta + 1 * HID);
    gemm_tc<HID, HID, false, true, true, true><<<dim3(ROWB, 1), 256>>>(ps, ph, ph, w_g2, b_g2, pt16);

    // layer 2: h2 never materialized; out += h2 @ w_fc + b_fc
    spmm_mma<<<dim3(4, GG), 256>>>(pt16, ps);
    bn_finalize<<<1, HID>>>(gamma + 2 * HID, beta + 2 * HID);
    gemm_tc<HID, OUTF, true, true, false, false><<<dim3(ROWB, 2), 256>>>(ps, ph, nullptr, w_fc, b_fc, out);
}